// round 9
// baseline (speedup 1.0000x reference)
#include <cuda_runtime.h>
#include <cuda_bf16.h>
#include <cuda_fp16.h>

constexpr int MAXN = 50000;
constexpr int MAXE = 1250000;
constexpr int D    = 64;
constexpr int H2   = 16;
constexpr int OUTW = 2;

// ---------------- device scratch ----------------
__device__ int    g_deg[MAXN];
__device__ int    g_start[MAXN];
__device__ int    g_fill[MAXN];
__device__ int    g_col[MAXE];
__device__ int    g_counter;
__device__ __half g_xl[(size_t)MAXN * D];
__device__ float  g_xr[(size_t)MAXN * D];
__device__ float  g_h[(size_t)MAXN * D];
__device__ __half g_hl[(size_t)MAXN * H2];
__device__ float  g_agg2[(size_t)MAXN * H2];

// ---------------- device bodies (verbatim logic from verified kernels) ----------------
__device__ __forceinline__ void hist_body(int bid, const int* __restrict__ dst, int E) {
    int i = (bid * 256 + threadIdx.x) * 8;
    if (i + 7 < E) {
        int4 d0 = *reinterpret_cast<const int4*>(dst + i);
        int4 d1 = *reinterpret_cast<const int4*>(dst + i + 4);
        atomicAdd(&g_deg[d0.x], 1); atomicAdd(&g_deg[d0.y], 1);
        atomicAdd(&g_deg[d0.z], 1); atomicAdd(&g_deg[d0.w], 1);
        atomicAdd(&g_deg[d1.x], 1); atomicAdd(&g_deg[d1.y], 1);
        atomicAdd(&g_deg[d1.z], 1); atomicAdd(&g_deg[d1.w], 1);
    } else {
        for (int k = i; k < E; k++) atomicAdd(&g_deg[dst[k]], 1);
    }
}

__device__ __forceinline__ void fill_body(int bid, const int* __restrict__ src,
                                          const int* __restrict__ dst, int E) {
    int i = (bid * 256 + threadIdx.x) * 8;
    if (i + 7 < E) {
        int4 s0 = *reinterpret_cast<const int4*>(src + i);
        int4 s1 = *reinterpret_cast<const int4*>(src + i + 4);
        int4 d0 = *reinterpret_cast<const int4*>(dst + i);
        int4 d1 = *reinterpret_cast<const int4*>(dst + i + 4);
        g_col[atomicAdd(&g_fill[d0.x], 1)] = s0.x;
        g_col[atomicAdd(&g_fill[d0.y], 1)] = s0.y;
        g_col[atomicAdd(&g_fill[d0.z], 1)] = s0.z;
        g_col[atomicAdd(&g_fill[d0.w], 1)] = s0.w;
        g_col[atomicAdd(&g_fill[d1.x], 1)] = s1.x;
        g_col[atomicAdd(&g_fill[d1.y], 1)] = s1.y;
        g_col[atomicAdd(&g_fill[d1.z], 1)] = s1.z;
        g_col[atomicAdd(&g_fill[d1.w], 1)] = s1.w;
    } else {
        for (int k = i; k < E; k++)
            g_col[atomicAdd(&g_fill[dst[k]], 1)] = src[k];
    }
}

// dense0 body: processes nodes [bi*64, bi*64+64) of [node_lo, node_hi)
struct Dense0Smem {
    float sWl[D * D];
    float sWr[D * D];
    float sb[D];
};

__device__ __forceinline__ void dense0_body(
    int bi, int node_lo, int node_hi,
    const float* __restrict__ x, const float* __restrict__ W1l,
    const float* __restrict__ W1r, const float* __restrict__ b1,
    __half* __restrict__ xl, float* __restrict__ xr, int n,
    Dense0Smem& sm
) {
    int tid = threadIdx.x;
    for (int i = tid; i < D * D; i += 256) { sm.sWl[i] = W1l[i]; sm.sWr[i] = W1r[i]; }
    if (tid < D) sm.sb[tid] = b1[tid];
    __syncthreads();

    int j = tid & 31;
    int w = tid >> 5;

    for (int s = 0; s < 2; s++) {
        int i0 = node_lo + bi * 64 + w * 4 + s * 32;
        if (i0 >= node_hi || i0 >= n) break;
        int lim = min(node_hi, n);
        int i1 = min(i0 + 1, lim - 1);
        int i2 = min(i0 + 2, lim - 1);
        int i3 = min(i0 + 3, lim - 1);
        const float4* xA = reinterpret_cast<const float4*>(x + (size_t)i0 * D);
        const float4* xB = reinterpret_cast<const float4*>(x + (size_t)i1 * D);
        const float4* xC = reinterpret_cast<const float4*>(x + (size_t)i2 * D);
        const float4* xD = reinterpret_cast<const float4*>(x + (size_t)i3 * D);

        float lA0 = 0.f, lA1 = 0.f, lB0 = 0.f, lB1 = 0.f;
        float lC0 = 0.f, lC1 = 0.f, lD0 = 0.f, lD1 = 0.f;
        float rA0 = sm.sb[j], rA1 = sm.sb[j + 32];
        float rB0 = sm.sb[j], rB1 = sm.sb[j + 32];
        float rC0 = sm.sb[j], rC1 = sm.sb[j + 32];
        float rD0 = sm.sb[j], rD1 = sm.sb[j + 32];

#pragma unroll
        for (int k4 = 0; k4 < 16; k4++) {
            float4 f0 = xA[k4], f1 = xB[k4], f2v = xC[k4], f3 = xD[k4];
            int k = k4 * 4;
#pragma unroll
            for (int c = 0; c < 4; c++) {
                float wl0 = sm.sWl[(k + c) * D + j];
                float wl1 = sm.sWl[(k + c) * D + j + 32];
                float wr0 = sm.sWr[(k + c) * D + j];
                float wr1 = sm.sWr[(k + c) * D + j + 32];
                float v0 = (&f0.x)[c], v1 = (&f1.x)[c], v2 = (&f2v.x)[c], v3 = (&f3.x)[c];
                lA0 += v0 * wl0; lA1 += v0 * wl1;  rA0 += v0 * wr0; rA1 += v0 * wr1;
                lB0 += v1 * wl0; lB1 += v1 * wl1;  rB0 += v1 * wr0; rB1 += v1 * wr1;
                lC0 += v2 * wl0; lC1 += v2 * wl1;  rC0 += v2 * wr0; rC1 += v2 * wr1;
                lD0 += v3 * wl0; lD1 += v3 * wl1;  rD0 += v3 * wr0; rD1 += v3 * wr1;
            }
        }
        xl[(size_t)i0 * D + j] = __float2half_rn(lA0);
        xl[(size_t)i0 * D + j + 32] = __float2half_rn(lA1);
        xr[(size_t)i0 * D + j] = rA0; xr[(size_t)i0 * D + j + 32] = rA1;
        if (i0 + 1 < lim) {
            xl[(size_t)i1 * D + j] = __float2half_rn(lB0);
            xl[(size_t)i1 * D + j + 32] = __float2half_rn(lB1);
            xr[(size_t)i1 * D + j] = rB0; xr[(size_t)i1 * D + j + 32] = rB1;
        }
        if (i0 + 2 < lim) {
            xl[(size_t)i2 * D + j] = __float2half_rn(lC0);
            xl[(size_t)i2 * D + j + 32] = __float2half_rn(lC1);
            xr[(size_t)i2 * D + j] = rC0; xr[(size_t)i2 * D + j + 32] = rC1;
        }
        if (i0 + 3 < lim) {
            xl[(size_t)i3 * D + j] = __float2half_rn(lD0);
            xl[(size_t)i3 * D + j + 32] = __float2half_rn(lD1);
            xr[(size_t)i3 * D + j] = rD0; xr[(size_t)i3 * D + j + 32] = rD1;
        }
    }
}

// ---------------- standalone kernels ----------------
__global__ void zero_kernel(int n) {
    int i = blockIdx.x * blockDim.x + threadIdx.x;
    if (i < n) g_deg[i] = 0;
    if (i == 0) g_counter = 0;
}

__global__ void alloc_kernel(int n) {
    int i = blockIdx.x * blockDim.x + threadIdx.x;
    int lane = threadIdx.x & 31;
    int deg = (i < n) ? g_deg[i] : 0;
    int incl = deg;
#pragma unroll
    for (int off = 1; off < 32; off <<= 1) {
        int v = __shfl_up_sync(0xffffffffu, incl, off);
        if (lane >= off) incl += v;
    }
    int excl = incl - deg;
    int base = 0;
    if (lane == 31) base = atomicAdd(&g_counter, incl);
    base = __shfl_sync(0xffffffffu, base, 31);
    if (i < n) {
        int s = base + excl;
        g_start[i] = s;
        g_fill[i]  = s;
    }
}

// ---- fused A: hist over all edges + dense0 on first half of nodes ----
__global__ void hist_dense0_kernel(const int* __restrict__ dst, int E, int histBlocks,
                                   const float* __restrict__ x, const float* __restrict__ W1l,
                                   const float* __restrict__ W1r, const float* __restrict__ b1,
                                   __half* __restrict__ xl, float* __restrict__ xr,
                                   int node_lo, int node_hi, int n) {
    __shared__ Dense0Smem sm;
    int bid = blockIdx.x;
    if (bid < histBlocks) {
        hist_body(bid, dst, E);
    } else {
        dense0_body(bid - histBlocks, node_lo, node_hi, x, W1l, W1r, b1, xl, xr, n, sm);
    }
}

// ---- fused B: fill over all edges + dense0 on second half of nodes ----
__global__ void fill_dense0_kernel(const int* __restrict__ src, const int* __restrict__ dst,
                                   int E, int fillBlocks,
                                   const float* __restrict__ x, const float* __restrict__ W1l,
                                   const float* __restrict__ W1r, const float* __restrict__ b1,
                                   __half* __restrict__ xl, float* __restrict__ xr,
                                   int node_lo, int node_hi, int n) {
    __shared__ Dense0Smem sm;
    int bid = blockIdx.x;
    if (bid < fillBlocks) {
        fill_body(bid, src, dst, E);
    } else {
        dense0_body(bid - fillBlocks, node_lo, node_hi, x, W1l, W1r, b1, xl, xr, n, sm);
    }
}

// ---------------- agg64_fused (verbatim from R8/passing) ----------------
__global__ void agg64_fused_kernel(const __half* __restrict__ xl, const float* __restrict__ xr,
                                   float* __restrict__ h, int n) {
    int node = blockIdx.x * 8 + (threadIdx.x >> 5);
    if (node >= n) return;
    int lane = threadIdx.x & 31;

    int rs  = g_start[node];
    int deg = g_deg[node];
    const __half2* f2 = reinterpret_cast<const __half2*>(xl);

    float2 acc = make_float2(0.f, 0.f);
    for (int base = 0; base < deg; base += 32) {
        int m = min(32, deg - base);
        int c = (lane < m) ? __ldg(&g_col[rs + base + lane]) : 0;
        int q = 0;
        for (; q + 4 <= m; q += 4) {
            int s0 = __shfl_sync(0xffffffffu, c, q + 0);
            int s1 = __shfl_sync(0xffffffffu, c, q + 1);
            int s2 = __shfl_sync(0xffffffffu, c, q + 2);
            int s3 = __shfl_sync(0xffffffffu, c, q + 3);
            float2 v0 = __half22float2(__ldg(&f2[(size_t)s0 * 32 + lane]));
            float2 v1 = __half22float2(__ldg(&f2[(size_t)s1 * 32 + lane]));
            float2 v2 = __half22float2(__ldg(&f2[(size_t)s2 * 32 + lane]));
            float2 v3 = __half22float2(__ldg(&f2[(size_t)s3 * 32 + lane]));
            acc.x += (v0.x + v1.x) + (v2.x + v3.x);
            acc.y += (v0.y + v1.y) + (v2.y + v3.y);
        }
        for (; q < m; q++) {
            int s = __shfl_sync(0xffffffffu, c, q);
            float2 v = __half22float2(__ldg(&f2[(size_t)s * 32 + lane]));
            acc.x += v.x; acc.y += v.y;
        }
    }
    float inv = 1.f / fmaxf((float)deg, 1.f);
    const float2* xr2 = reinterpret_cast<const float2*>(xr);
    float2 r = __ldg(&xr2[(size_t)node * 32 + lane]);
    float2 hv;
    hv.x = fmaxf(acc.x * inv + r.x, 0.f);
    hv.y = fmaxf(acc.y * inv + r.y, 0.f);
    reinterpret_cast<float2*>(h)[(size_t)node * 32 + lane] = hv;
}

// ---------------- dense1b (verbatim from R8/passing) ----------------
__global__ void dense1b_kernel(const float* __restrict__ h, const float* __restrict__ W2l,
                               __half* __restrict__ hl, int n) {
    __shared__ float sW[D * H2];
    int tid = threadIdx.x;
    for (int i = tid; i < D * H2; i += 256) sW[i] = W2l[i];
    __syncthreads();

    int j  = tid & 15;
    int il = tid >> 4;
    int base = blockIdx.x * 64;

    for (int s = 0; s < 64; s += 16) {
        int i = base + il + s;
        if (i >= n) continue;
        const float4* h4 = reinterpret_cast<const float4*>(h + (size_t)i * D);
        float acc = 0.f;
#pragma unroll
        for (int k4 = 0; k4 < 16; k4++) {
            float4 hv = h4[k4];
            int k = k4 * 4;
            acc += hv.x * sW[(k + 0) * H2 + j];
            acc += hv.y * sW[(k + 1) * H2 + j];
            acc += hv.z * sW[(k + 2) * H2 + j];
            acc += hv.w * sW[(k + 3) * H2 + j];
        }
        hl[(size_t)i * H2 + j] = __float2half_rn(acc);
    }
}

// ---------------- agg16 (verbatim from R8/passing) ----------------
__global__ void agg16_kernel(const __half* __restrict__ feat, float* __restrict__ out, int n) {
    int node = blockIdx.x * 16 + (threadIdx.x >> 4);
    if (node >= n) return;
    int hlane = threadIdx.x & 15;

    int rs  = g_start[node];
    int deg = g_deg[node];

    float acc = 0.f;
    for (int base = 0; base < deg; base += 16) {
        int m = min(16, deg - base);
        int c = (hlane < m) ? __ldg(&g_col[rs + base + hlane]) : 0;
        int q = 0;
        for (; q + 4 <= m; q += 4) {
            int s0 = __shfl_sync(0xffffffffu, c, q + 0, 16);
            int s1 = __shfl_sync(0xffffffffu, c, q + 1, 16);
            int s2 = __shfl_sync(0xffffffffu, c, q + 2, 16);
            int s3 = __shfl_sync(0xffffffffu, c, q + 3, 16);
            float v0 = __half2float(__ldg(&feat[(size_t)s0 * H2 + hlane]));
            float v1 = __half2float(__ldg(&feat[(size_t)s1 * H2 + hlane]));
            float v2 = __half2float(__ldg(&feat[(size_t)s2 * H2 + hlane]));
            float v3 = __half2float(__ldg(&feat[(size_t)s3 * H2 + hlane]));
            acc += (v0 + v1) + (v2 + v3);
        }
        for (; q < m; q++) {
            int s = __shfl_sync(0xffffffffu, c, q, 16);
            acc += __half2float(__ldg(&feat[(size_t)s * H2 + hlane]));
        }
    }
    out[(size_t)node * H2 + hlane] = acc / fmaxf((float)deg, 1.f);
}

// ---------------- dense2 + fc (verbatim from R8/passing) ----------------
__global__ void dense2_kernel(const float* __restrict__ agg2, const float* __restrict__ h,
                              const float* __restrict__ W2r, const float* __restrict__ b2,
                              const float* __restrict__ Wfc, const float* __restrict__ bfc,
                              float* __restrict__ out, int n) {
    __shared__ float sWr[D * H2];
    __shared__ float sb2[H2];
    __shared__ float sWfc[H2 * OUTW];
    __shared__ float sbfc[OUTW];
    int tid = threadIdx.x;
    for (int i = tid; i < D * H2; i += 256) sWr[i] = W2r[i];
    if (tid < H2) sb2[tid] = b2[tid];
    if (tid < H2 * OUTW) sWfc[tid] = Wfc[tid];
    if (tid < OUTW) sbfc[tid] = bfc[tid];
    __syncthreads();

    int j  = tid & 15;
    int il = tid >> 4;
    int base = blockIdx.x * 64;

    for (int s = 0; s < 64; s += 16) {
        int i = base + il + s;
        bool valid = (i < n);
        int ic = valid ? i : (n - 1);
        const float4* h4 = reinterpret_cast<const float4*>(h + (size_t)ic * D);
        float acc = sb2[j] + agg2[(size_t)ic * H2 + j];
#pragma unroll
        for (int k4 = 0; k4 < 16; k4++) {
            float4 hv = h4[k4];
            int k = k4 * 4;
            acc += hv.x * sWr[(k + 0) * H2 + j];
            acc += hv.y * sWr[(k + 1) * H2 + j];
            acc += hv.z * sWr[(k + 2) * H2 + j];
            acc += hv.w * sWr[(k + 3) * H2 + j];
        }
        float o0 = acc * sWfc[j * OUTW + 0];
        float o1 = acc * sWfc[j * OUTW + 1];
#pragma unroll
        for (int off = 8; off >= 1; off >>= 1) {
            o0 += __shfl_down_sync(0xffffffffu, o0, off, 16);
            o1 += __shfl_down_sync(0xffffffffu, o1, off, 16);
        }
        if (j == 0 && valid) {
            out[(size_t)i * OUTW + 0] = o0 + sbfc[0];
            out[(size_t)i * OUTW + 1] = o1 + sbfc[1];
        }
    }
}

// ---------------- launcher (single stream, kernels only) ----------------
extern "C" void kernel_launch(void* const* d_in, const int* in_sizes, int n_in,
                              void* d_out, int out_size) {
    const float* x   = (const float*)d_in[0];
    const int*   e   = (const int*)d_in[1];
    const float* W1l = (const float*)d_in[2];
    const float* b1  = (const float*)d_in[3];
    const float* W1r = (const float*)d_in[4];
    const float* W2l = (const float*)d_in[5];
    const float* b2  = (const float*)d_in[6];
    const float* W2r = (const float*)d_in[7];
    const float* Wfc = (const float*)d_in[8];
    const float* bfc = (const float*)d_in[9];
    float* out = (float*)d_out;

    int n = in_sizes[0] / D;
    int E = in_sizes[1] / 2;
    const int* src = e;
    const int* dst = e + E;

    __half *xlp, *hlp;
    float *xrp, *hp, *agg2p;
    cudaGetSymbolAddress((void**)&xlp, g_xl);
    cudaGetSymbolAddress((void**)&xrp, g_xr);
    cudaGetSymbolAddress((void**)&hp, g_h);
    cudaGetSymbolAddress((void**)&hlp, g_hl);
    cudaGetSymbolAddress((void**)&agg2p, g_agg2);

    int edgeBlocks = (E / 8 + 255) / 256;           // hist/fill block count
    int denseBlocksTotal = (n + 63) / 64;           // dense0 total blocks
    int denseA = denseBlocksTotal / 2;              // co-scheduled with hist
    int denseB = denseBlocksTotal - denseA;         // co-scheduled with fill
    int nodeSplit = denseA * 64;                    // node boundary

    // 1) zero
    zero_kernel<<<(n + 255) / 256, 256>>>(n);
    // 2) hist (all edges) || dense0 on nodes [0, nodeSplit)
    hist_dense0_kernel<<<edgeBlocks + denseA, 256>>>(dst, E, edgeBlocks,
                                                     x, W1l, W1r, b1, xlp, xrp,
                                                     0, nodeSplit, n);
    // 3) alloc
    alloc_kernel<<<(n + 255) / 256, 256>>>(n);
    // 4) fill (all edges) || dense0 on nodes [nodeSplit, n)
    fill_dense0_kernel<<<edgeBlocks + denseB, 256>>>(src, dst, E, edgeBlocks,
                                                     x, W1l, W1r, b1, xlp, xrp,
                                                     nodeSplit, n, n);
    // 5) aggregate + fused epilogue
    agg64_fused_kernel<<<(n + 7) / 8, 256>>>(xlp, xrp, hp, n);
    // 6-8) layer 2 + fc
    dense1b_kernel<<<(n + 63) / 64, 256>>>(hp, W2l, hlp, n);
    agg16_kernel<<<(n + 15) / 16, 256>>>(hlp, agg2p, n);
    dense2_kernel<<<(n + 63) / 64, 256>>>(agg2p, hp, W2r, b2, Wfc, bfc, out, n);
}

// round 10
// speedup vs baseline: 1.0527x; 1.0527x over previous
#include <cuda_runtime.h>
#include <cuda_bf16.h>
#include <cuda_fp16.h>

constexpr int MAXN = 50000;
constexpr int MAXE = 1250000;
constexpr int D    = 64;
constexpr int H2   = 16;
constexpr int OUTW = 2;

// ---------------- device scratch ----------------
__device__ int    g_deg[MAXN];
__device__ int    g_start[MAXN];
__device__ int    g_rank[MAXE];             // edge rank within its dst (from hist)
__device__ int    g_col[MAXE];
__device__ int    g_counter;
__device__ __half g_xl[(size_t)MAXN * D];
__device__ float  g_xr[(size_t)MAXN * D];
__device__ float  g_h[(size_t)MAXN * D];
__device__ __half g_hl[(size_t)MAXN * H2];
__device__ float  g_agg2[(size_t)MAXN * H2];

// ---------------- CSR build ----------------
__global__ void zero_kernel(int n) {
    int i = blockIdx.x * blockDim.x + threadIdx.x;
    if (i < n) g_deg[i] = 0;
    if (i == 0) g_counter = 0;
}

// hist: count degrees AND record each edge's rank (atomic return value).
__global__ void hist_kernel(const int* __restrict__ dst, int E) {
    int i = (blockIdx.x * blockDim.x + threadIdx.x) * 8;
    if (i + 7 < E) {
        int4 d0 = *reinterpret_cast<const int4*>(dst + i);
        int4 d1 = *reinterpret_cast<const int4*>(dst + i + 4);
        int4 r0, r1;
        r0.x = atomicAdd(&g_deg[d0.x], 1);
        r0.y = atomicAdd(&g_deg[d0.y], 1);
        r0.z = atomicAdd(&g_deg[d0.z], 1);
        r0.w = atomicAdd(&g_deg[d0.w], 1);
        r1.x = atomicAdd(&g_deg[d1.x], 1);
        r1.y = atomicAdd(&g_deg[d1.y], 1);
        r1.z = atomicAdd(&g_deg[d1.z], 1);
        r1.w = atomicAdd(&g_deg[d1.w], 1);
        *reinterpret_cast<int4*>(g_rank + i)     = r0;
        *reinterpret_cast<int4*>(g_rank + i + 4) = r1;
    } else {
        for (int k = i; k < E; k++) g_rank[k] = atomicAdd(&g_deg[dst[k]], 1);
    }
}

__global__ void alloc_kernel(int n) {
    int i = blockIdx.x * blockDim.x + threadIdx.x;
    int lane = threadIdx.x & 31;
    int deg = (i < n) ? g_deg[i] : 0;
    int incl = deg;
#pragma unroll
    for (int off = 1; off < 32; off <<= 1) {
        int v = __shfl_up_sync(0xffffffffu, incl, off);
        if (lane >= off) incl += v;
    }
    int excl = incl - deg;
    int base = 0;
    if (lane == 31) base = atomicAdd(&g_counter, incl);
    base = __shfl_sync(0xffffffffu, base, 31);
    if (i < n) g_start[i] = base + excl;
}

// fill: atomic-free — position = start[dst] + rank.
__global__ void fill_kernel(const int* __restrict__ src, const int* __restrict__ dst, int E) {
    int i = (blockIdx.x * blockDim.x + threadIdx.x) * 8;
    if (i + 7 < E) {
        int4 s0 = *reinterpret_cast<const int4*>(src + i);
        int4 s1 = *reinterpret_cast<const int4*>(src + i + 4);
        int4 d0 = *reinterpret_cast<const int4*>(dst + i);
        int4 d1 = *reinterpret_cast<const int4*>(dst + i + 4);
        int4 r0 = *reinterpret_cast<const int4*>(g_rank + i);
        int4 r1 = *reinterpret_cast<const int4*>(g_rank + i + 4);
        g_col[__ldg(&g_start[d0.x]) + r0.x] = s0.x;
        g_col[__ldg(&g_start[d0.y]) + r0.y] = s0.y;
        g_col[__ldg(&g_start[d0.z]) + r0.z] = s0.z;
        g_col[__ldg(&g_start[d0.w]) + r0.w] = s0.w;
        g_col[__ldg(&g_start[d1.x]) + r1.x] = s1.x;
        g_col[__ldg(&g_start[d1.y]) + r1.y] = s1.y;
        g_col[__ldg(&g_start[d1.z]) + r1.z] = s1.z;
        g_col[__ldg(&g_start[d1.w]) + r1.w] = s1.w;
    } else {
        for (int k = i; k < E; k++)
            g_col[__ldg(&g_start[dst[k]]) + g_rank[k]] = src[k];
    }
}

// ---------------- dense0: xl = fp16(x@W1l), xr = x@W1r + b1 (verbatim R8) ----------------
__global__ void dense0_kernel(const float* __restrict__ x, const float* __restrict__ W1l,
                              const float* __restrict__ W1r, const float* __restrict__ b1,
                              __half* __restrict__ xl, float* __restrict__ xr, int n) {
    __shared__ float sWl[D * D];
    __shared__ float sWr[D * D];
    __shared__ float sb[D];
    int tid = threadIdx.x;
    for (int i = tid; i < D * D; i += 256) { sWl[i] = W1l[i]; sWr[i] = W1r[i]; }
    if (tid < D) sb[tid] = b1[tid];
    __syncthreads();

    int j = tid & 31;
    int w = tid >> 5;

    for (int s = 0; s < 2; s++) {
        int i0 = blockIdx.x * 64 + w * 4 + s * 32;
        if (i0 >= n) break;
        int i1 = min(i0 + 1, n - 1);
        int i2 = min(i0 + 2, n - 1);
        int i3 = min(i0 + 3, n - 1);
        const float4* xA = reinterpret_cast<const float4*>(x + (size_t)i0 * D);
        const float4* xB = reinterpret_cast<const float4*>(x + (size_t)i1 * D);
        const float4* xC = reinterpret_cast<const float4*>(x + (size_t)i2 * D);
        const float4* xD = reinterpret_cast<const float4*>(x + (size_t)i3 * D);

        float lA0 = 0.f, lA1 = 0.f, lB0 = 0.f, lB1 = 0.f;
        float lC0 = 0.f, lC1 = 0.f, lD0 = 0.f, lD1 = 0.f;
        float rA0 = sb[j], rA1 = sb[j + 32];
        float rB0 = sb[j], rB1 = sb[j + 32];
        float rC0 = sb[j], rC1 = sb[j + 32];
        float rD0 = sb[j], rD1 = sb[j + 32];

#pragma unroll
        for (int k4 = 0; k4 < 16; k4++) {
            float4 f0 = xA[k4], f1 = xB[k4], f2v = xC[k4], f3 = xD[k4];
            int k = k4 * 4;
#pragma unroll
            for (int c = 0; c < 4; c++) {
                float wl0 = sWl[(k + c) * D + j];
                float wl1 = sWl[(k + c) * D + j + 32];
                float wr0 = sWr[(k + c) * D + j];
                float wr1 = sWr[(k + c) * D + j + 32];
                float v0 = (&f0.x)[c], v1 = (&f1.x)[c], v2 = (&f2v.x)[c], v3 = (&f3.x)[c];
                lA0 += v0 * wl0; lA1 += v0 * wl1;  rA0 += v0 * wr0; rA1 += v0 * wr1;
                lB0 += v1 * wl0; lB1 += v1 * wl1;  rB0 += v1 * wr0; rB1 += v1 * wr1;
                lC0 += v2 * wl0; lC1 += v2 * wl1;  rC0 += v2 * wr0; rC1 += v2 * wr1;
                lD0 += v3 * wl0; lD1 += v3 * wl1;  rD0 += v3 * wr0; rD1 += v3 * wr1;
            }
        }
        xl[(size_t)i0 * D + j] = __float2half_rn(lA0);
        xl[(size_t)i0 * D + j + 32] = __float2half_rn(lA1);
        xr[(size_t)i0 * D + j] = rA0; xr[(size_t)i0 * D + j + 32] = rA1;
        if (i0 + 1 < n) {
            xl[(size_t)i1 * D + j] = __float2half_rn(lB0);
            xl[(size_t)i1 * D + j + 32] = __float2half_rn(lB1);
            xr[(size_t)i1 * D + j] = rB0; xr[(size_t)i1 * D + j + 32] = rB1;
        }
        if (i0 + 2 < n) {
            xl[(size_t)i2 * D + j] = __float2half_rn(lC0);
            xl[(size_t)i2 * D + j + 32] = __float2half_rn(lC1);
            xr[(size_t)i2 * D + j] = rC0; xr[(size_t)i2 * D + j + 32] = rC1;
        }
        if (i0 + 3 < n) {
            xl[(size_t)i3 * D + j] = __float2half_rn(lD0);
            xl[(size_t)i3 * D + j + 32] = __float2half_rn(lD1);
            xr[(size_t)i3 * D + j] = rD0; xr[(size_t)i3 * D + j + 32] = rD1;
        }
    }
}

// ---------------- agg64_fused (verbatim R8) ----------------
__global__ void agg64_fused_kernel(const __half* __restrict__ xl, const float* __restrict__ xr,
                                   float* __restrict__ h, int n) {
    int node = blockIdx.x * 8 + (threadIdx.x >> 5);
    if (node >= n) return;
    int lane = threadIdx.x & 31;

    int rs  = g_start[node];
    int deg = g_deg[node];
    const __half2* f2 = reinterpret_cast<const __half2*>(xl);

    float2 acc = make_float2(0.f, 0.f);
    for (int base = 0; base < deg; base += 32) {
        int m = min(32, deg - base);
        int c = (lane < m) ? __ldg(&g_col[rs + base + lane]) : 0;
        int q = 0;
        for (; q + 4 <= m; q += 4) {
            int s0 = __shfl_sync(0xffffffffu, c, q + 0);
            int s1 = __shfl_sync(0xffffffffu, c, q + 1);
            int s2 = __shfl_sync(0xffffffffu, c, q + 2);
            int s3 = __shfl_sync(0xffffffffu, c, q + 3);
            float2 v0 = __half22float2(__ldg(&f2[(size_t)s0 * 32 + lane]));
            float2 v1 = __half22float2(__ldg(&f2[(size_t)s1 * 32 + lane]));
            float2 v2 = __half22float2(__ldg(&f2[(size_t)s2 * 32 + lane]));
            float2 v3 = __half22float2(__ldg(&f2[(size_t)s3 * 32 + lane]));
            acc.x += (v0.x + v1.x) + (v2.x + v3.x);
            acc.y += (v0.y + v1.y) + (v2.y + v3.y);
        }
        for (; q < m; q++) {
            int s = __shfl_sync(0xffffffffu, c, q);
            float2 v = __half22float2(__ldg(&f2[(size_t)s * 32 + lane]));
            acc.x += v.x; acc.y += v.y;
        }
    }
    float inv = 1.f / fmaxf((float)deg, 1.f);
    const float2* xr2 = reinterpret_cast<const float2*>(xr);
    float2 r = __ldg(&xr2[(size_t)node * 32 + lane]);
    float2 hv;
    hv.x = fmaxf(acc.x * inv + r.x, 0.f);
    hv.y = fmaxf(acc.y * inv + r.y, 0.f);
    reinterpret_cast<float2*>(h)[(size_t)node * 32 + lane] = hv;
}

// ---------------- dense1b (verbatim R8) ----------------
__global__ void dense1b_kernel(const float* __restrict__ h, const float* __restrict__ W2l,
                               __half* __restrict__ hl, int n) {
    __shared__ float sW[D * H2];
    int tid = threadIdx.x;
    for (int i = tid; i < D * H2; i += 256) sW[i] = W2l[i];
    __syncthreads();

    int j  = tid & 15;
    int il = tid >> 4;
    int base = blockIdx.x * 64;

    for (int s = 0; s < 64; s += 16) {
        int i = base + il + s;
        if (i >= n) continue;
        const float4* h4 = reinterpret_cast<const float4*>(h + (size_t)i * D);
        float acc = 0.f;
#pragma unroll
        for (int k4 = 0; k4 < 16; k4++) {
            float4 hv = h4[k4];
            int k = k4 * 4;
            acc += hv.x * sW[(k + 0) * H2 + j];
            acc += hv.y * sW[(k + 1) * H2 + j];
            acc += hv.z * sW[(k + 2) * H2 + j];
            acc += hv.w * sW[(k + 3) * H2 + j];
        }
        hl[(size_t)i * H2 + j] = __float2half_rn(acc);
    }
}

// ---------------- agg16 (verbatim R8) ----------------
__global__ void agg16_kernel(const __half* __restrict__ feat, float* __restrict__ out, int n) {
    int node = blockIdx.x * 16 + (threadIdx.x >> 4);
    if (node >= n) return;
    int hlane = threadIdx.x & 15;

    int rs  = g_start[node];
    int deg = g_deg[node];

    float acc = 0.f;
    for (int base = 0; base < deg; base += 16) {
        int m = min(16, deg - base);
        int c = (hlane < m) ? __ldg(&g_col[rs + base + hlane]) : 0;
        int q = 0;
        for (; q + 4 <= m; q += 4) {
            int s0 = __shfl_sync(0xffffffffu, c, q + 0, 16);
            int s1 = __shfl_sync(0xffffffffu, c, q + 1, 16);
            int s2 = __shfl_sync(0xffffffffu, c, q + 2, 16);
            int s3 = __shfl_sync(0xffffffffu, c, q + 3, 16);
            float v0 = __half2float(__ldg(&feat[(size_t)s0 * H2 + hlane]));
            float v1 = __half2float(__ldg(&feat[(size_t)s1 * H2 + hlane]));
            float v2 = __half2float(__ldg(&feat[(size_t)s2 * H2 + hlane]));
            float v3 = __half2float(__ldg(&feat[(size_t)s3 * H2 + hlane]));
            acc += (v0 + v1) + (v2 + v3);
        }
        for (; q < m; q++) {
            int s = __shfl_sync(0xffffffffu, c, q, 16);
            acc += __half2float(__ldg(&feat[(size_t)s * H2 + hlane]));
        }
    }
    out[(size_t)node * H2 + hlane] = acc / fmaxf((float)deg, 1.f);
}

// ---------------- dense2 + fc (verbatim R8) ----------------
__global__ void dense2_kernel(const float* __restrict__ agg2, const float* __restrict__ h,
                              const float* __restrict__ W2r, const float* __restrict__ b2,
                              const float* __restrict__ Wfc, const float* __restrict__ bfc,
                              float* __restrict__ out, int n) {
    __shared__ float sWr[D * H2];
    __shared__ float sb2[H2];
    __shared__ float sWfc[H2 * OUTW];
    __shared__ float sbfc[OUTW];
    int tid = threadIdx.x;
    for (int i = tid; i < D * H2; i += 256) sWr[i] = W2r[i];
    if (tid < H2) sb2[tid] = b2[tid];
    if (tid < H2 * OUTW) sWfc[tid] = Wfc[tid];
    if (tid < OUTW) sbfc[tid] = bfc[tid];
    __syncthreads();

    int j  = tid & 15;
    int il = tid >> 4;
    int base = blockIdx.x * 64;

    for (int s = 0; s < 64; s += 16) {
        int i = base + il + s;
        bool valid = (i < n);
        int ic = valid ? i : (n - 1);
        const float4* h4 = reinterpret_cast<const float4*>(h + (size_t)ic * D);
        float acc = sb2[j] + agg2[(size_t)ic * H2 + j];
#pragma unroll
        for (int k4 = 0; k4 < 16; k4++) {
            float4 hv = h4[k4];
            int k = k4 * 4;
            acc += hv.x * sWr[(k + 0) * H2 + j];
            acc += hv.y * sWr[(k + 1) * H2 + j];
            acc += hv.z * sWr[(k + 2) * H2 + j];
            acc += hv.w * sWr[(k + 3) * H2 + j];
        }
        float o0 = acc * sWfc[j * OUTW + 0];
        float o1 = acc * sWfc[j * OUTW + 1];
#pragma unroll
        for (int off = 8; off >= 1; off >>= 1) {
            o0 += __shfl_down_sync(0xffffffffu, o0, off, 16);
            o1 += __shfl_down_sync(0xffffffffu, o1, off, 16);
        }
        if (j == 0 && valid) {
            out[(size_t)i * OUTW + 0] = o0 + sbfc[0];
            out[(size_t)i * OUTW + 1] = o1 + sbfc[1];
        }
    }
}

// ---------------- launcher (single stream, kernels only) ----------------
extern "C" void kernel_launch(void* const* d_in, const int* in_sizes, int n_in,
                              void* d_out, int out_size) {
    const float* x   = (const float*)d_in[0];
    const int*   e   = (const int*)d_in[1];
    const float* W1l = (const float*)d_in[2];
    const float* b1  = (const float*)d_in[3];
    const float* W1r = (const float*)d_in[4];
    const float* W2l = (const float*)d_in[5];
    const float* b2  = (const float*)d_in[6];
    const float* W2r = (const float*)d_in[7];
    const float* Wfc = (const float*)d_in[8];
    const float* bfc = (const float*)d_in[9];
    float* out = (float*)d_out;

    int n = in_sizes[0] / D;
    int E = in_sizes[1] / 2;
    const int* src = e;
    const int* dst = e + E;

    __half *xlp, *hlp;
    float *xrp, *hp, *agg2p;
    cudaGetSymbolAddress((void**)&xlp, g_xl);
    cudaGetSymbolAddress((void**)&xrp, g_xr);
    cudaGetSymbolAddress((void**)&hp, g_h);
    cudaGetSymbolAddress((void**)&hlp, g_hl);
    cudaGetSymbolAddress((void**)&agg2p, g_agg2);

    // CSR build (rank-based: fill is atomic-free)
    zero_kernel<<<(n + 255) / 256, 256>>>(n);
    hist_kernel<<<(E / 8 + 255) / 256, 256>>>(dst, E);
    alloc_kernel<<<(n + 255) / 256, 256>>>(n);
    fill_kernel<<<(E / 8 + 255) / 256, 256>>>(src, dst, E);

    // layer 1
    dense0_kernel<<<(n + 63) / 64, 256>>>(x, W1l, W1r, b1, xlp, xrp, n);
    agg64_fused_kernel<<<(n + 7) / 8, 256>>>(xlp, xrp, hp, n);

    // layer 2 + fc
    dense1b_kernel<<<(n + 63) / 64, 256>>>(hp, W2l, hlp, n);
    agg16_kernel<<<(n + 15) / 16, 256>>>(hlp, agg2p, n);
    dense2_kernel<<<(n + 63) / 64, 256>>>(agg2p, hp, W2r, b2, Wfc, bfc, out, n);
}

// round 11
// speedup vs baseline: 1.1013x; 1.0463x over previous
#include <cuda_runtime.h>
#include <cuda_bf16.h>
#include <cuda_fp16.h>

constexpr int MAXN = 50000;
constexpr int MAXE = 1250000;
constexpr int D    = 64;
constexpr int H2   = 16;
constexpr int OUTW = 2;

// ---------------- device scratch ----------------
__device__ int    g_deg[MAXN];
__device__ int    g_start[MAXN];
__device__ int    g_rank[MAXE];
__device__ int    g_col[MAXE];
__device__ int    g_counter;
__device__ __half g_xl[(size_t)MAXN * D];
__device__ float  g_xr[(size_t)MAXN * D];
__device__ float  g_h[(size_t)MAXN * D];
__device__ __half g_hl[(size_t)MAXN * H2];
__device__ float  g_agg2[(size_t)MAXN * H2];

// ---------------- CSR build (verbatim R10/passing) ----------------
__global__ void zero_kernel(int n) {
    int i = blockIdx.x * blockDim.x + threadIdx.x;
    if (i < n) g_deg[i] = 0;
    if (i == 0) g_counter = 0;
}

__global__ void hist_kernel(const int* __restrict__ dst, int E) {
    int i = (blockIdx.x * blockDim.x + threadIdx.x) * 8;
    if (i + 7 < E) {
        int4 d0 = *reinterpret_cast<const int4*>(dst + i);
        int4 d1 = *reinterpret_cast<const int4*>(dst + i + 4);
        int4 r0, r1;
        r0.x = atomicAdd(&g_deg[d0.x], 1);
        r0.y = atomicAdd(&g_deg[d0.y], 1);
        r0.z = atomicAdd(&g_deg[d0.z], 1);
        r0.w = atomicAdd(&g_deg[d0.w], 1);
        r1.x = atomicAdd(&g_deg[d1.x], 1);
        r1.y = atomicAdd(&g_deg[d1.y], 1);
        r1.z = atomicAdd(&g_deg[d1.z], 1);
        r1.w = atomicAdd(&g_deg[d1.w], 1);
        *reinterpret_cast<int4*>(g_rank + i)     = r0;
        *reinterpret_cast<int4*>(g_rank + i + 4) = r1;
    } else {
        for (int k = i; k < E; k++) g_rank[k] = atomicAdd(&g_deg[dst[k]], 1);
    }
}

__global__ void alloc_kernel(int n) {
    int i = blockIdx.x * blockDim.x + threadIdx.x;
    int lane = threadIdx.x & 31;
    int deg = (i < n) ? g_deg[i] : 0;
    int incl = deg;
#pragma unroll
    for (int off = 1; off < 32; off <<= 1) {
        int v = __shfl_up_sync(0xffffffffu, incl, off);
        if (lane >= off) incl += v;
    }
    int excl = incl - deg;
    int base = 0;
    if (lane == 31) base = atomicAdd(&g_counter, incl);
    base = __shfl_sync(0xffffffffu, base, 31);
    if (i < n) g_start[i] = base + excl;
}

__global__ void fill_kernel(const int* __restrict__ src, const int* __restrict__ dst, int E) {
    int i = (blockIdx.x * blockDim.x + threadIdx.x) * 8;
    if (i + 7 < E) {
        int4 s0 = *reinterpret_cast<const int4*>(src + i);
        int4 s1 = *reinterpret_cast<const int4*>(src + i + 4);
        int4 d0 = *reinterpret_cast<const int4*>(dst + i);
        int4 d1 = *reinterpret_cast<const int4*>(dst + i + 4);
        int4 r0 = *reinterpret_cast<const int4*>(g_rank + i);
        int4 r1 = *reinterpret_cast<const int4*>(g_rank + i + 4);
        g_col[__ldg(&g_start[d0.x]) + r0.x] = s0.x;
        g_col[__ldg(&g_start[d0.y]) + r0.y] = s0.y;
        g_col[__ldg(&g_start[d0.z]) + r0.z] = s0.z;
        g_col[__ldg(&g_start[d0.w]) + r0.w] = s0.w;
        g_col[__ldg(&g_start[d1.x]) + r1.x] = s1.x;
        g_col[__ldg(&g_start[d1.y]) + r1.y] = s1.y;
        g_col[__ldg(&g_start[d1.z]) + r1.z] = s1.z;
        g_col[__ldg(&g_start[d1.w]) + r1.w] = s1.w;
    } else {
        for (int k = i; k < E; k++)
            g_col[__ldg(&g_start[dst[k]]) + g_rank[k]] = src[k];
    }
}

// ---------------- dense0 (verbatim R10/passing) ----------------
__global__ void dense0_kernel(const float* __restrict__ x, const float* __restrict__ W1l,
                              const float* __restrict__ W1r, const float* __restrict__ b1,
                              __half* __restrict__ xl, float* __restrict__ xr, int n) {
    __shared__ float sWl[D * D];
    __shared__ float sWr[D * D];
    __shared__ float sb[D];
    int tid = threadIdx.x;
    for (int i = tid; i < D * D; i += 256) { sWl[i] = W1l[i]; sWr[i] = W1r[i]; }
    if (tid < D) sb[tid] = b1[tid];
    __syncthreads();

    int j = tid & 31;
    int w = tid >> 5;

    for (int s = 0; s < 2; s++) {
        int i0 = blockIdx.x * 64 + w * 4 + s * 32;
        if (i0 >= n) break;
        int i1 = min(i0 + 1, n - 1);
        int i2 = min(i0 + 2, n - 1);
        int i3 = min(i0 + 3, n - 1);
        const float4* xA = reinterpret_cast<const float4*>(x + (size_t)i0 * D);
        const float4* xB = reinterpret_cast<const float4*>(x + (size_t)i1 * D);
        const float4* xC = reinterpret_cast<const float4*>(x + (size_t)i2 * D);
        const float4* xD = reinterpret_cast<const float4*>(x + (size_t)i3 * D);

        float lA0 = 0.f, lA1 = 0.f, lB0 = 0.f, lB1 = 0.f;
        float lC0 = 0.f, lC1 = 0.f, lD0 = 0.f, lD1 = 0.f;
        float rA0 = sb[j], rA1 = sb[j + 32];
        float rB0 = sb[j], rB1 = sb[j + 32];
        float rC0 = sb[j], rC1 = sb[j + 32];
        float rD0 = sb[j], rD1 = sb[j + 32];

#pragma unroll
        for (int k4 = 0; k4 < 16; k4++) {
            float4 f0 = xA[k4], f1 = xB[k4], f2v = xC[k4], f3 = xD[k4];
            int k = k4 * 4;
#pragma unroll
            for (int c = 0; c < 4; c++) {
                float wl0 = sWl[(k + c) * D + j];
                float wl1 = sWl[(k + c) * D + j + 32];
                float wr0 = sWr[(k + c) * D + j];
                float wr1 = sWr[(k + c) * D + j + 32];
                float v0 = (&f0.x)[c], v1 = (&f1.x)[c], v2 = (&f2v.x)[c], v3 = (&f3.x)[c];
                lA0 += v0 * wl0; lA1 += v0 * wl1;  rA0 += v0 * wr0; rA1 += v0 * wr1;
                lB0 += v1 * wl0; lB1 += v1 * wl1;  rB0 += v1 * wr0; rB1 += v1 * wr1;
                lC0 += v2 * wl0; lC1 += v2 * wl1;  rC0 += v2 * wr0; rC1 += v2 * wr1;
                lD0 += v3 * wl0; lD1 += v3 * wl1;  rD0 += v3 * wr0; rD1 += v3 * wr1;
            }
        }
        xl[(size_t)i0 * D + j] = __float2half_rn(lA0);
        xl[(size_t)i0 * D + j + 32] = __float2half_rn(lA1);
        xr[(size_t)i0 * D + j] = rA0; xr[(size_t)i0 * D + j + 32] = rA1;
        if (i0 + 1 < n) {
            xl[(size_t)i1 * D + j] = __float2half_rn(lB0);
            xl[(size_t)i1 * D + j + 32] = __float2half_rn(lB1);
            xr[(size_t)i1 * D + j] = rB0; xr[(size_t)i1 * D + j + 32] = rB1;
        }
        if (i0 + 2 < n) {
            xl[(size_t)i2 * D + j] = __float2half_rn(lC0);
            xl[(size_t)i2 * D + j + 32] = __float2half_rn(lC1);
            xr[(size_t)i2 * D + j] = rC0; xr[(size_t)i2 * D + j + 32] = rC1;
        }
        if (i0 + 3 < n) {
            xl[(size_t)i3 * D + j] = __float2half_rn(lD0);
            xl[(size_t)i3 * D + j + 32] = __float2half_rn(lD1);
            xr[(size_t)i3 * D + j] = rD0; xr[(size_t)i3 * D + j + 32] = rD1;
        }
    }
}

// ---------------- agg64_fused: 2 edges per LDG/shfl ----------------
// Warp per node. Lanes split into 2 halves of 16; each half covers one edge's
// full 128B fp16 row (16 lanes x uint2). One shfl broadcasts 2 indices.
__global__ void agg64_fused_kernel(const __half* __restrict__ xl, const float* __restrict__ xr,
                                   float* __restrict__ h, int n) {
    int node = blockIdx.x * 8 + (threadIdx.x >> 5);
    if (node >= n) return;
    int lane = threadIdx.x & 31;
    int hf   = lane >> 4;   // 0/1: which edge of the pair
    int sub  = lane & 15;   // 8B chunk within row (4 features)

    int rs  = g_start[node];
    int deg = g_deg[node];
    const uint2* f = reinterpret_cast<const uint2*>(xl);  // row = 16 uint2

    float4 acc = make_float4(0.f, 0.f, 0.f, 0.f);
    for (int base = 0; base < deg; base += 32) {
        int m = min(32, deg - base);
        int c = (lane < m) ? __ldg(&g_col[rs + base + lane]) : 0;
#pragma unroll 4
        for (int q = 0; q < m; q += 2) {
            int e = q + hf;                                   // <= 31 always
            int idx = __shfl_sync(0xffffffffu, c, e);
            uint2 v = __ldg(&f[(size_t)idx * 16 + sub]);      // idx=0 safe when e>=m
            float2 a = __half22float2(*reinterpret_cast<__half2*>(&v.x));
            float2 b = __half22float2(*reinterpret_cast<__half2*>(&v.y));
            if (e < m) {
                acc.x += a.x; acc.y += a.y; acc.z += b.x; acc.w += b.y;
            }
        }
    }
    // combine the two half-warp partial sums
    acc.x += __shfl_xor_sync(0xffffffffu, acc.x, 16);
    acc.y += __shfl_xor_sync(0xffffffffu, acc.y, 16);
    acc.z += __shfl_xor_sync(0xffffffffu, acc.z, 16);
    acc.w += __shfl_xor_sync(0xffffffffu, acc.w, 16);

    if (hf == 0) {
        float inv = 1.f / fmaxf((float)deg, 1.f);
        const float4* xr4 = reinterpret_cast<const float4*>(xr);  // row = 16 float4
        float4 r = __ldg(&xr4[(size_t)node * 16 + sub]);
        float4 hv;
        hv.x = fmaxf(acc.x * inv + r.x, 0.f);
        hv.y = fmaxf(acc.y * inv + r.y, 0.f);
        hv.z = fmaxf(acc.z * inv + r.z, 0.f);
        hv.w = fmaxf(acc.w * inv + r.w, 0.f);
        reinterpret_cast<float4*>(h)[(size_t)node * 16 + sub] = hv;
    }
}

// ---------------- dense1b (verbatim R10/passing) ----------------
__global__ void dense1b_kernel(const float* __restrict__ h, const float* __restrict__ W2l,
                               __half* __restrict__ hl, int n) {
    __shared__ float sW[D * H2];
    int tid = threadIdx.x;
    for (int i = tid; i < D * H2; i += 256) sW[i] = W2l[i];
    __syncthreads();

    int j  = tid & 15;
    int il = tid >> 4;
    int base = blockIdx.x * 64;

    for (int s = 0; s < 64; s += 16) {
        int i = base + il + s;
        if (i >= n) continue;
        const float4* h4 = reinterpret_cast<const float4*>(h + (size_t)i * D);
        float acc = 0.f;
#pragma unroll
        for (int k4 = 0; k4 < 16; k4++) {
            float4 hv = h4[k4];
            int k = k4 * 4;
            acc += hv.x * sW[(k + 0) * H2 + j];
            acc += hv.y * sW[(k + 1) * H2 + j];
            acc += hv.z * sW[(k + 2) * H2 + j];
            acc += hv.w * sW[(k + 3) * H2 + j];
        }
        hl[(size_t)i * H2 + j] = __float2half_rn(acc);
    }
}

// ---------------- agg16: 8 edges per LDG/shfl ----------------
// Warp per node. 8 groups of 4 lanes; each group covers one edge's 32B fp16
// row (4 lanes x uint2). One shfl broadcasts 8 indices.
__global__ void agg16_kernel(const __half* __restrict__ feat, float* __restrict__ out, int n) {
    int node = blockIdx.x * 8 + (threadIdx.x >> 5);
    if (node >= n) return;
    int lane = threadIdx.x & 31;
    int grp = lane >> 2;    // 0..7: which edge of the octet
    int sub = lane & 3;     // 8B chunk within row (4 features)

    int rs  = g_start[node];
    int deg = g_deg[node];
    const uint2* f = reinterpret_cast<const uint2*>(feat);  // row = 4 uint2

    float4 acc = make_float4(0.f, 0.f, 0.f, 0.f);
    for (int base = 0; base < deg; base += 32) {
        int m = min(32, deg - base);
        int c = (lane < m) ? __ldg(&g_col[rs + base + lane]) : 0;
#pragma unroll 4
        for (int q = 0; q < m; q += 8) {
            int e = q + grp;                                  // <= 31 always
            int idx = __shfl_sync(0xffffffffu, c, e);
            uint2 v = __ldg(&f[(size_t)idx * 4 + sub]);
            float2 a = __half22float2(*reinterpret_cast<__half2*>(&v.x));
            float2 b = __half22float2(*reinterpret_cast<__half2*>(&v.y));
            if (e < m) {
                acc.x += a.x; acc.y += a.y; acc.z += b.x; acc.w += b.y;
            }
        }
    }
    // combine the 8 group partial sums (lanes with equal sub share features)
    acc.x += __shfl_xor_sync(0xffffffffu, acc.x, 4);
    acc.y += __shfl_xor_sync(0xffffffffu, acc.y, 4);
    acc.z += __shfl_xor_sync(0xffffffffu, acc.z, 4);
    acc.w += __shfl_xor_sync(0xffffffffu, acc.w, 4);
    acc.x += __shfl_xor_sync(0xffffffffu, acc.x, 8);
    acc.y += __shfl_xor_sync(0xffffffffu, acc.y, 8);
    acc.z += __shfl_xor_sync(0xffffffffu, acc.z, 8);
    acc.w += __shfl_xor_sync(0xffffffffu, acc.w, 8);
    acc.x += __shfl_xor_sync(0xffffffffu, acc.x, 16);
    acc.y += __shfl_xor_sync(0xffffffffu, acc.y, 16);
    acc.z += __shfl_xor_sync(0xffffffffu, acc.z, 16);
    acc.w += __shfl_xor_sync(0xffffffffu, acc.w, 16);

    if (grp == 0) {
        float inv = 1.f / fmaxf((float)deg, 1.f);
        float4 o;
        o.x = acc.x * inv; o.y = acc.y * inv; o.z = acc.z * inv; o.w = acc.w * inv;
        reinterpret_cast<float4*>(out)[(size_t)node * 4 + sub] = o;  // row = 4 float4
    }
}

// ---------------- dense2 + fc (verbatim R10/passing) ----------------
__global__ void dense2_kernel(const float* __restrict__ agg2, const float* __restrict__ h,
                              const float* __restrict__ W2r, const float* __restrict__ b2,
                              const float* __restrict__ Wfc, const float* __restrict__ bfc,
                              float* __restrict__ out, int n) {
    __shared__ float sWr[D * H2];
    __shared__ float sb2[H2];
    __shared__ float sWfc[H2 * OUTW];
    __shared__ float sbfc[OUTW];
    int tid = threadIdx.x;
    for (int i = tid; i < D * H2; i += 256) sWr[i] = W2r[i];
    if (tid < H2) sb2[tid] = b2[tid];
    if (tid < H2 * OUTW) sWfc[tid] = Wfc[tid];
    if (tid < OUTW) sbfc[tid] = bfc[tid];
    __syncthreads();

    int j  = tid & 15;
    int il = tid >> 4;
    int base = blockIdx.x * 64;

    for (int s = 0; s < 64; s += 16) {
        int i = base + il + s;
        bool valid = (i < n);
        int ic = valid ? i : (n - 1);
        const float4* h4 = reinterpret_cast<const float4*>(h + (size_t)ic * D);
        float acc = sb2[j] + agg2[(size_t)ic * H2 + j];
#pragma unroll
        for (int k4 = 0; k4 < 16; k4++) {
            float4 hv = h4[k4];
            int k = k4 * 4;
            acc += hv.x * sWr[(k + 0) * H2 + j];
            acc += hv.y * sWr[(k + 1) * H2 + j];
            acc += hv.z * sWr[(k + 2) * H2 + j];
            acc += hv.w * sWr[(k + 3) * H2 + j];
        }
        float o0 = acc * sWfc[j * OUTW + 0];
        float o1 = acc * sWfc[j * OUTW + 1];
#pragma unroll
        for (int off = 8; off >= 1; off >>= 1) {
            o0 += __shfl_down_sync(0xffffffffu, o0, off, 16);
            o1 += __shfl_down_sync(0xffffffffu, o1, off, 16);
        }
        if (j == 0 && valid) {
            out[(size_t)i * OUTW + 0] = o0 + sbfc[0];
            out[(size_t)i * OUTW + 1] = o1 + sbfc[1];
        }
    }
}

// ---------------- launcher (single stream, kernels only) ----------------
extern "C" void kernel_launch(void* const* d_in, const int* in_sizes, int n_in,
                              void* d_out, int out_size) {
    const float* x   = (const float*)d_in[0];
    const int*   e   = (const int*)d_in[1];
    const float* W1l = (const float*)d_in[2];
    const float* b1  = (const float*)d_in[3];
    const float* W1r = (const float*)d_in[4];
    const float* W2l = (const float*)d_in[5];
    const float* b2  = (const float*)d_in[6];
    const float* W2r = (const float*)d_in[7];
    const float* Wfc = (const float*)d_in[8];
    const float* bfc = (const float*)d_in[9];
    float* out = (float*)d_out;

    int n = in_sizes[0] / D;
    int E = in_sizes[1] / 2;
    const int* src = e;
    const int* dst = e + E;

    __half *xlp, *hlp;
    float *xrp, *hp, *agg2p;
    cudaGetSymbolAddress((void**)&xlp, g_xl);
    cudaGetSymbolAddress((void**)&xrp, g_xr);
    cudaGetSymbolAddress((void**)&hp, g_h);
    cudaGetSymbolAddress((void**)&hlp, g_hl);
    cudaGetSymbolAddress((void**)&agg2p, g_agg2);

    // CSR build
    zero_kernel<<<(n + 255) / 256, 256>>>(n);
    hist_kernel<<<(E / 8 + 255) / 256, 256>>>(dst, E);
    alloc_kernel<<<(n + 255) / 256, 256>>>(n);
    fill_kernel<<<(E / 8 + 255) / 256, 256>>>(src, dst, E);

    // layer 1
    dense0_kernel<<<(n + 63) / 64, 256>>>(x, W1l, W1r, b1, xlp, xrp, n);
    agg64_fused_kernel<<<(n + 7) / 8, 256>>>(xlp, xrp, hp, n);

    // layer 2 + fc
    dense1b_kernel<<<(n + 63) / 64, 256>>>(hp, W2l, hlp, n);
    agg16_kernel<<<(n + 7) / 8, 256>>>(hlp, agg2p, n);
    dense2_kernel<<<(n + 63) / 64, 256>>>(agg2p, hp, W2r, b2, Wfc, bfc, out, n);
}

// round 12
// speedup vs baseline: 1.1500x; 1.0442x over previous
#include <cuda_runtime.h>
#include <cuda_bf16.h>
#include <cuda_fp16.h>

constexpr int MAXN = 50000;
constexpr int MAXE = 1250000;
constexpr int D    = 64;
constexpr int H2   = 16;
constexpr int OUTW = 2;

// ---------------- device scratch ----------------
__device__ int    g_deg[MAXN];
__device__ int    g_start[MAXN];
__device__ int    g_rank[MAXE];
__device__ int    g_col[MAXE];
__device__ int    g_counter;
__device__ __half g_xl[(size_t)MAXN * D];
__device__ float  g_xr[(size_t)MAXN * D];
__device__ float  g_h[(size_t)MAXN * D];
__device__ __half g_hl[(size_t)MAXN * H2];
__device__ float  g_hr[(size_t)MAXN * H2];

// ---------------- hist (verbatim R11/passing) ----------------
__global__ void hist_kernel(const int* __restrict__ dst, int E) {
    int i = (blockIdx.x * blockDim.x + threadIdx.x) * 8;
    if (i + 7 < E) {
        int4 d0 = *reinterpret_cast<const int4*>(dst + i);
        int4 d1 = *reinterpret_cast<const int4*>(dst + i + 4);
        int4 r0, r1;
        r0.x = atomicAdd(&g_deg[d0.x], 1);
        r0.y = atomicAdd(&g_deg[d0.y], 1);
        r0.z = atomicAdd(&g_deg[d0.z], 1);
        r0.w = atomicAdd(&g_deg[d0.w], 1);
        r1.x = atomicAdd(&g_deg[d1.x], 1);
        r1.y = atomicAdd(&g_deg[d1.y], 1);
        r1.z = atomicAdd(&g_deg[d1.z], 1);
        r1.w = atomicAdd(&g_deg[d1.w], 1);
        *reinterpret_cast<int4*>(g_rank + i)     = r0;
        *reinterpret_cast<int4*>(g_rank + i + 4) = r1;
    } else {
        for (int k = i; k < E; k++) g_rank[k] = atomicAdd(&g_deg[dst[k]], 1);
    }
}

__global__ void alloc_kernel(int n) {
    int i = blockIdx.x * blockDim.x + threadIdx.x;
    int lane = threadIdx.x & 31;
    int deg = (i < n) ? g_deg[i] : 0;
    int incl = deg;
#pragma unroll
    for (int off = 1; off < 32; off <<= 1) {
        int v = __shfl_up_sync(0xffffffffu, incl, off);
        if (lane >= off) incl += v;
    }
    int excl = incl - deg;
    int base = 0;
    if (lane == 31) base = atomicAdd(&g_counter, incl);
    base = __shfl_sync(0xffffffffu, base, 31);
    if (i < n) g_start[i] = base + excl;
}

__global__ void fill_kernel(const int* __restrict__ src, const int* __restrict__ dst, int E) {
    int i = (blockIdx.x * blockDim.x + threadIdx.x) * 8;
    if (i + 7 < E) {
        int4 s0 = *reinterpret_cast<const int4*>(src + i);
        int4 s1 = *reinterpret_cast<const int4*>(src + i + 4);
        int4 d0 = *reinterpret_cast<const int4*>(dst + i);
        int4 d1 = *reinterpret_cast<const int4*>(dst + i + 4);
        int4 r0 = *reinterpret_cast<const int4*>(g_rank + i);
        int4 r1 = *reinterpret_cast<const int4*>(g_rank + i + 4);
        g_col[__ldg(&g_start[d0.x]) + r0.x] = s0.x;
        g_col[__ldg(&g_start[d0.y]) + r0.y] = s0.y;
        g_col[__ldg(&g_start[d0.z]) + r0.z] = s0.z;
        g_col[__ldg(&g_start[d0.w]) + r0.w] = s0.w;
        g_col[__ldg(&g_start[d1.x]) + r1.x] = s1.x;
        g_col[__ldg(&g_start[d1.y]) + r1.y] = s1.y;
        g_col[__ldg(&g_start[d1.z]) + r1.z] = s1.z;
        g_col[__ldg(&g_start[d1.w]) + r1.w] = s1.w;
    } else {
        for (int k = i; k < E; k++)
            g_col[__ldg(&g_start[dst[k]]) + g_rank[k]] = src[k];
    }
}

// ---------------- dense0z: zero(deg,counter) prologue + dense0 (R11 body) ----------------
__global__ void dense0z_kernel(const float* __restrict__ x, const float* __restrict__ W1l,
                               const float* __restrict__ W1r, const float* __restrict__ b1,
                               __half* __restrict__ xl, float* __restrict__ xr, int n) {
    // zero prologue: grid*256 >= n guaranteed by launch config
    {
        int zi = blockIdx.x * 256 + threadIdx.x;
        if (zi < n) g_deg[zi] = 0;
        if (zi == 0) g_counter = 0;
    }

    __shared__ float sWl[D * D];
    __shared__ float sWr[D * D];
    __shared__ float sb[D];
    int tid = threadIdx.x;
    for (int i = tid; i < D * D; i += 256) { sWl[i] = W1l[i]; sWr[i] = W1r[i]; }
    if (tid < D) sb[tid] = b1[tid];
    __syncthreads();

    int j = tid & 31;
    int w = tid >> 5;

    for (int s = 0; s < 2; s++) {
        int i0 = blockIdx.x * 64 + w * 4 + s * 32;
        if (i0 >= n) break;
        int i1 = min(i0 + 1, n - 1);
        int i2 = min(i0 + 2, n - 1);
        int i3 = min(i0 + 3, n - 1);
        const float4* xA = reinterpret_cast<const float4*>(x + (size_t)i0 * D);
        const float4* xB = reinterpret_cast<const float4*>(x + (size_t)i1 * D);
        const float4* xC = reinterpret_cast<const float4*>(x + (size_t)i2 * D);
        const float4* xD = reinterpret_cast<const float4*>(x + (size_t)i3 * D);

        float lA0 = 0.f, lA1 = 0.f, lB0 = 0.f, lB1 = 0.f;
        float lC0 = 0.f, lC1 = 0.f, lD0 = 0.f, lD1 = 0.f;
        float rA0 = sb[j], rA1 = sb[j + 32];
        float rB0 = sb[j], rB1 = sb[j + 32];
        float rC0 = sb[j], rC1 = sb[j + 32];
        float rD0 = sb[j], rD1 = sb[j + 32];

#pragma unroll
        for (int k4 = 0; k4 < 16; k4++) {
            float4 f0 = xA[k4], f1 = xB[k4], f2v = xC[k4], f3 = xD[k4];
            int k = k4 * 4;
#pragma unroll
            for (int c = 0; c < 4; c++) {
                float wl0 = sWl[(k + c) * D + j];
                float wl1 = sWl[(k + c) * D + j + 32];
                float wr0 = sWr[(k + c) * D + j];
                float wr1 = sWr[(k + c) * D + j + 32];
                float v0 = (&f0.x)[c], v1 = (&f1.x)[c], v2 = (&f2v.x)[c], v3 = (&f3.x)[c];
                lA0 += v0 * wl0; lA1 += v0 * wl1;  rA0 += v0 * wr0; rA1 += v0 * wr1;
                lB0 += v1 * wl0; lB1 += v1 * wl1;  rB0 += v1 * wr0; rB1 += v1 * wr1;
                lC0 += v2 * wl0; lC1 += v2 * wl1;  rC0 += v2 * wr0; rC1 += v2 * wr1;
                lD0 += v3 * wl0; lD1 += v3 * wl1;  rD0 += v3 * wr0; rD1 += v3 * wr1;
            }
        }
        xl[(size_t)i0 * D + j] = __float2half_rn(lA0);
        xl[(size_t)i0 * D + j + 32] = __float2half_rn(lA1);
        xr[(size_t)i0 * D + j] = rA0; xr[(size_t)i0 * D + j + 32] = rA1;
        if (i0 + 1 < n) {
            xl[(size_t)i1 * D + j] = __float2half_rn(lB0);
            xl[(size_t)i1 * D + j + 32] = __float2half_rn(lB1);
            xr[(size_t)i1 * D + j] = rB0; xr[(size_t)i1 * D + j + 32] = rB1;
        }
        if (i0 + 2 < n) {
            xl[(size_t)i2 * D + j] = __float2half_rn(lC0);
            xl[(size_t)i2 * D + j + 32] = __float2half_rn(lC1);
            xr[(size_t)i2 * D + j] = rC0; xr[(size_t)i2 * D + j + 32] = rC1;
        }
        if (i0 + 3 < n) {
            xl[(size_t)i3 * D + j] = __float2half_rn(lD0);
            xl[(size_t)i3 * D + j + 32] = __float2half_rn(lD1);
            xr[(size_t)i3 * D + j] = rD0; xr[(size_t)i3 * D + j + 32] = rD1;
        }
    }
}

// ---------------- agg64_fused (verbatim R11/passing) ----------------
__global__ void agg64_fused_kernel(const __half* __restrict__ xl, const float* __restrict__ xr,
                                   float* __restrict__ h, int n) {
    int node = blockIdx.x * 8 + (threadIdx.x >> 5);
    if (node >= n) return;
    int lane = threadIdx.x & 31;
    int hf   = lane >> 4;
    int sub  = lane & 15;

    int rs  = g_start[node];
    int deg = g_deg[node];
    const uint2* f = reinterpret_cast<const uint2*>(xl);

    float4 acc = make_float4(0.f, 0.f, 0.f, 0.f);
    for (int base = 0; base < deg; base += 32) {
        int m = min(32, deg - base);
        int c = (lane < m) ? __ldg(&g_col[rs + base + lane]) : 0;
#pragma unroll 4
        for (int q = 0; q < m; q += 2) {
            int e = q + hf;
            int idx = __shfl_sync(0xffffffffu, c, e);
            uint2 v = __ldg(&f[(size_t)idx * 16 + sub]);
            float2 a = __half22float2(*reinterpret_cast<__half2*>(&v.x));
            float2 b = __half22float2(*reinterpret_cast<__half2*>(&v.y));
            if (e < m) {
                acc.x += a.x; acc.y += a.y; acc.z += b.x; acc.w += b.y;
            }
        }
    }
    acc.x += __shfl_xor_sync(0xffffffffu, acc.x, 16);
    acc.y += __shfl_xor_sync(0xffffffffu, acc.y, 16);
    acc.z += __shfl_xor_sync(0xffffffffu, acc.z, 16);
    acc.w += __shfl_xor_sync(0xffffffffu, acc.w, 16);

    if (hf == 0) {
        float inv = 1.f / fmaxf((float)deg, 1.f);
        const float4* xr4 = reinterpret_cast<const float4*>(xr);
        float4 r = __ldg(&xr4[(size_t)node * 16 + sub]);
        float4 hv;
        hv.x = fmaxf(acc.x * inv + r.x, 0.f);
        hv.y = fmaxf(acc.y * inv + r.y, 0.f);
        hv.z = fmaxf(acc.z * inv + r.z, 0.f);
        hv.w = fmaxf(acc.w * inv + r.w, 0.f);
        reinterpret_cast<float4*>(h)[(size_t)node * 16 + sub] = hv;
    }
}

// ---------------- dense12: hl = fp16(h@W2l), hr = h@W2r + b2 (reads h once) ----------------
// Built on the verified dense1b skeleton with dual weights/accumulators.
__global__ void dense12_kernel(const float* __restrict__ h, const float* __restrict__ W2l,
                               const float* __restrict__ W2r, const float* __restrict__ b2,
                               __half* __restrict__ hl, float* __restrict__ hr, int n) {
    __shared__ float sWl[D * H2];
    __shared__ float sWr[D * H2];
    __shared__ float sb[H2];
    int tid = threadIdx.x;
    for (int i = tid; i < D * H2; i += 256) { sWl[i] = W2l[i]; sWr[i] = W2r[i]; }
    if (tid < H2) sb[tid] = b2[tid];
    __syncthreads();

    int j  = tid & 15;
    int il = tid >> 4;
    int base = blockIdx.x * 64;

    for (int s = 0; s < 64; s += 16) {
        int i = base + il + s;
        if (i >= n) continue;
        const float4* h4 = reinterpret_cast<const float4*>(h + (size_t)i * D);
        float al = 0.f, ar = sb[j];
#pragma unroll
        for (int k4 = 0; k4 < 16; k4++) {
            float4 hv = h4[k4];
            int k = k4 * 4;
            al += hv.x * sWl[(k + 0) * H2 + j] + hv.y * sWl[(k + 1) * H2 + j]
                + hv.z * sWl[(k + 2) * H2 + j] + hv.w * sWl[(k + 3) * H2 + j];
            ar += hv.x * sWr[(k + 0) * H2 + j] + hv.y * sWr[(k + 1) * H2 + j]
                + hv.z * sWr[(k + 2) * H2 + j] + hv.w * sWr[(k + 3) * H2 + j];
        }
        hl[(size_t)i * H2 + j] = __float2half_rn(al);
        hr[(size_t)i * H2 + j] = ar;
    }
}

// ---------------- agg16_final: out = (mean-gather(hl) + hr) @ Wfc + bfc ----------------
// Built on the verified R11 agg16 skeleton (warp per node, 8 edges/LDG+shfl).
__global__ void agg16_final_kernel(const __half* __restrict__ hl, const float* __restrict__ hr,
                                   const float* __restrict__ Wfc, const float* __restrict__ bfc,
                                   float* __restrict__ out, int n) {
    int node = blockIdx.x * 8 + (threadIdx.x >> 5);
    if (node >= n) return;
    int lane = threadIdx.x & 31;
    int grp = lane >> 2;
    int sub = lane & 3;

    int rs  = g_start[node];
    int deg = g_deg[node];
    const uint2* f = reinterpret_cast<const uint2*>(hl);

    float4 acc = make_float4(0.f, 0.f, 0.f, 0.f);
    for (int base = 0; base < deg; base += 32) {
        int m = min(32, deg - base);
        int c = (lane < m) ? __ldg(&g_col[rs + base + lane]) : 0;
#pragma unroll 4
        for (int q = 0; q < m; q += 8) {
            int e = q + grp;
            int idx = __shfl_sync(0xffffffffu, c, e);
            uint2 v = __ldg(&f[(size_t)idx * 4 + sub]);
            float2 a = __half22float2(*reinterpret_cast<__half2*>(&v.x));
            float2 b = __half22float2(*reinterpret_cast<__half2*>(&v.y));
            if (e < m) {
                acc.x += a.x; acc.y += a.y; acc.z += b.x; acc.w += b.y;
            }
        }
    }
    // combine across the 8 groups: after these, EVERY lane holds the full sum
    // for its sub (features 4*sub .. 4*sub+3)
    acc.x += __shfl_xor_sync(0xffffffffu, acc.x, 4);
    acc.y += __shfl_xor_sync(0xffffffffu, acc.y, 4);
    acc.z += __shfl_xor_sync(0xffffffffu, acc.z, 4);
    acc.w += __shfl_xor_sync(0xffffffffu, acc.w, 4);
    acc.x += __shfl_xor_sync(0xffffffffu, acc.x, 8);
    acc.y += __shfl_xor_sync(0xffffffffu, acc.y, 8);
    acc.z += __shfl_xor_sync(0xffffffffu, acc.z, 8);
    acc.w += __shfl_xor_sync(0xffffffffu, acc.w, 8);
    acc.x += __shfl_xor_sync(0xffffffffu, acc.x, 16);
    acc.y += __shfl_xor_sync(0xffffffffu, acc.y, 16);
    acc.z += __shfl_xor_sync(0xffffffffu, acc.z, 16);
    acc.w += __shfl_xor_sync(0xffffffffu, acc.w, 16);

    // epilogue: h2 = mean + hr, out = h2 @ Wfc + bfc
    float inv = 1.f / fmaxf((float)deg, 1.f);
    const float4* hr4 = reinterpret_cast<const float4*>(hr);  // row = 4 float4
    float4 r = __ldg(&hr4[(size_t)node * 4 + sub]);
    float a0 = acc.x * inv + r.x;
    float a1 = acc.y * inv + r.y;
    float a2 = acc.z * inv + r.z;
    float a3 = acc.w * inv + r.w;

    int jb = sub * 4;  // first feature index for this lane
    float o0 = a0 * __ldg(&Wfc[(jb + 0) * OUTW + 0]) + a1 * __ldg(&Wfc[(jb + 1) * OUTW + 0])
             + a2 * __ldg(&Wfc[(jb + 2) * OUTW + 0]) + a3 * __ldg(&Wfc[(jb + 3) * OUTW + 0]);
    float o1 = a0 * __ldg(&Wfc[(jb + 0) * OUTW + 1]) + a1 * __ldg(&Wfc[(jb + 1) * OUTW + 1])
             + a2 * __ldg(&Wfc[(jb + 2) * OUTW + 1]) + a3 * __ldg(&Wfc[(jb + 3) * OUTW + 1]);
    // reduce across sub (xor 1, 2 touch only the sub bits)
    o0 += __shfl_xor_sync(0xffffffffu, o0, 1);
    o1 += __shfl_xor_sync(0xffffffffu, o1, 1);
    o0 += __shfl_xor_sync(0xffffffffu, o0, 2);
    o1 += __shfl_xor_sync(0xffffffffu, o1, 2);

    if (lane == 0) {
        out[(size_t)node * OUTW + 0] = o0 + __ldg(&bfc[0]);
        out[(size_t)node * OUTW + 1] = o1 + __ldg(&bfc[1]);
    }
}

// ---------------- launcher (single stream, kernels only) ----------------
extern "C" void kernel_launch(void* const* d_in, const int* in_sizes, int n_in,
                              void* d_out, int out_size) {
    const float* x   = (const float*)d_in[0];
    const int*   e   = (const int*)d_in[1];
    const float* W1l = (const float*)d_in[2];
    const float* b1  = (const float*)d_in[3];
    const float* W1r = (const float*)d_in[4];
    const float* W2l = (const float*)d_in[5];
    const float* b2  = (const float*)d_in[6];
    const float* W2r = (const float*)d_in[7];
    const float* Wfc = (const float*)d_in[8];
    const float* bfc = (const float*)d_in[9];
    float* out = (float*)d_out;

    int n = in_sizes[0] / D;
    int E = in_sizes[1] / 2;
    const int* src = e;
    const int* dst = e + E;

    __half *xlp, *hlp;
    float *xrp, *hp, *hrp;
    cudaGetSymbolAddress((void**)&xlp, g_xl);
    cudaGetSymbolAddress((void**)&xrp, g_xr);
    cudaGetSymbolAddress((void**)&hp, g_h);
    cudaGetSymbolAddress((void**)&hlp, g_hl);
    cudaGetSymbolAddress((void**)&hrp, g_hr);

    // dense0 + zero prologue (must run before hist; grid*256 >= n)
    int dense0Blocks = (n + 63) / 64;   // 782 blocks * 256 threads = 200K >= n
    dense0z_kernel<<<dense0Blocks, 256>>>(x, W1l, W1r, b1, xlp, xrp, n);

    // CSR build
    hist_kernel<<<(E / 8 + 255) / 256, 256>>>(dst, E);
    alloc_kernel<<<(n + 255) / 256, 256>>>(n);
    fill_kernel<<<(E / 8 + 255) / 256, 256>>>(src, dst, E);

    // layer 1 aggregate
    agg64_fused_kernel<<<(n + 7) / 8, 256>>>(xlp, xrp, hp, n);

    // layer 2 + fc (fused tail)
    dense12_kernel<<<(n + 63) / 64, 256>>>(hp, W2l, W2r, b2, hlp, hrp, n);
    agg16_final_kernel<<<(n + 7) / 8, 256>>>(hlp, hrp, Wfc, bfc, out, n);
}

// round 13
// speedup vs baseline: 1.1893x; 1.0341x over previous
#include <cuda_runtime.h>
#include <cuda_bf16.h>
#include <cuda_fp16.h>
#include <mma.h>

using namespace nvcuda;

constexpr int MAXN = 50000;
constexpr int MAXE = 1250000;
constexpr int D    = 64;
constexpr int H2   = 16;
constexpr int OUTW = 2;

// ---------------- device scratch ----------------
__device__ int    g_deg[MAXN];
__device__ int    g_start[MAXN];
__device__ int    g_rank[MAXE];
__device__ int    g_col[MAXE];
__device__ int    g_counter;
__device__ __half g_xl[(size_t)MAXN * D];
__device__ float  g_xr[(size_t)MAXN * D];
__device__ float  g_h[(size_t)MAXN * D];
__device__ __half g_hl[(size_t)MAXN * H2];
__device__ float  g_hr[(size_t)MAXN * H2];

// ---------------- hist (verbatim R12/passing) ----------------
__global__ void hist_kernel(const int* __restrict__ dst, int E) {
    int i = (blockIdx.x * blockDim.x + threadIdx.x) * 8;
    if (i + 7 < E) {
        int4 d0 = *reinterpret_cast<const int4*>(dst + i);
        int4 d1 = *reinterpret_cast<const int4*>(dst + i + 4);
        int4 r0, r1;
        r0.x = atomicAdd(&g_deg[d0.x], 1);
        r0.y = atomicAdd(&g_deg[d0.y], 1);
        r0.z = atomicAdd(&g_deg[d0.z], 1);
        r0.w = atomicAdd(&g_deg[d0.w], 1);
        r1.x = atomicAdd(&g_deg[d1.x], 1);
        r1.y = atomicAdd(&g_deg[d1.y], 1);
        r1.z = atomicAdd(&g_deg[d1.z], 1);
        r1.w = atomicAdd(&g_deg[d1.w], 1);
        *reinterpret_cast<int4*>(g_rank + i)     = r0;
        *reinterpret_cast<int4*>(g_rank + i + 4) = r1;
    } else {
        for (int k = i; k < E; k++) g_rank[k] = atomicAdd(&g_deg[dst[k]], 1);
    }
}

__global__ void alloc_kernel(int n) {
    int i = blockIdx.x * blockDim.x + threadIdx.x;
    int lane = threadIdx.x & 31;
    int deg = (i < n) ? g_deg[i] : 0;
    int incl = deg;
#pragma unroll
    for (int off = 1; off < 32; off <<= 1) {
        int v = __shfl_up_sync(0xffffffffu, incl, off);
        if (lane >= off) incl += v;
    }
    int excl = incl - deg;
    int base = 0;
    if (lane == 31) base = atomicAdd(&g_counter, incl);
    base = __shfl_sync(0xffffffffu, base, 31);
    if (i < n) g_start[i] = base + excl;
}

__global__ void fill_kernel(const int* __restrict__ src, const int* __restrict__ dst, int E) {
    int i = (blockIdx.x * blockDim.x + threadIdx.x) * 8;
    if (i + 7 < E) {
        int4 s0 = *reinterpret_cast<const int4*>(src + i);
        int4 s1 = *reinterpret_cast<const int4*>(src + i + 4);
        int4 d0 = *reinterpret_cast<const int4*>(dst + i);
        int4 d1 = *reinterpret_cast<const int4*>(dst + i + 4);
        int4 r0 = *reinterpret_cast<const int4*>(g_rank + i);
        int4 r1 = *reinterpret_cast<const int4*>(g_rank + i + 4);
        g_col[__ldg(&g_start[d0.x]) + r0.x] = s0.x;
        g_col[__ldg(&g_start[d0.y]) + r0.y] = s0.y;
        g_col[__ldg(&g_start[d0.z]) + r0.z] = s0.z;
        g_col[__ldg(&g_start[d0.w]) + r0.w] = s0.w;
        g_col[__ldg(&g_start[d1.x]) + r1.x] = s1.x;
        g_col[__ldg(&g_start[d1.y]) + r1.y] = s1.y;
        g_col[__ldg(&g_start[d1.z]) + r1.z] = s1.z;
        g_col[__ldg(&g_start[d1.w]) + r1.w] = s1.w;
    } else {
        for (int k = i; k < E; k++)
            g_col[__ldg(&g_start[dst[k]]) + g_rank[k]] = src[k];
    }
}

// ---------------- dense0z (wmma tensor-core version) ----------------
// Block: 256 threads (8 warps), 64 nodes x 128 outputs (xl 0..63 | xr 64..127).
// smem union: phase 1 uses sW (fp16 64x128) + sX (fp16 64x64) inside the
// 32KB float buffer; phase 2 overwrites it with fp32 staging (64x128).
__global__ void dense0z_kernel(const float* __restrict__ x, const float* __restrict__ W1l,
                               const float* __restrict__ W1r, const float* __restrict__ b1,
                               __half* __restrict__ xl, float* __restrict__ xr, int n) {
    // zero prologue: grid*256 >= n guaranteed by launch config
    {
        int zi = blockIdx.x * 256 + threadIdx.x;
        if (zi < n) g_deg[zi] = 0;
        if (zi == 0) g_counter = 0;
    }

    __shared__ float sOut[64 * 128];   // 32KB; aliased in phase 1
    __shared__ float sb[D];
    __half* sW = reinterpret_cast<__half*>(sOut);          // 64x128 fp16 = 16KB
    __half* sX = reinterpret_cast<__half*>(sOut + 4096);   // 64x64  fp16 =  8KB

    int tid = threadIdx.x;
    int base = blockIdx.x * 64;

    // phase 1a: weights -> fp16 smem [k][j]; j<64 = W1l, j>=64 = W1r
    for (int i = tid; i < D * D; i += 256) {
        int k = i >> 6, j = i & 63;
        sW[k * 128 + j]      = __float2half_rn(W1l[i]);
        sW[k * 128 + 64 + j] = __float2half_rn(W1r[i]);
    }
    if (tid < D) sb[tid] = b1[tid];

    // phase 1b: x tile -> fp16 smem (row clamped; stores guarded later)
    {
        int row  = tid >> 2;          // 0..63
        int col0 = (tid & 3) * 16;    // 0,16,32,48
        int gr = min(base + row, n - 1);
        const float4* xp = reinterpret_cast<const float4*>(x + (size_t)gr * D + col0);
#pragma unroll
        for (int q = 0; q < 4; q++) {
            float4 v = __ldg(&xp[q]);
            int c = col0 + q * 4;
            sX[row * 64 + c + 0] = __float2half_rn(v.x);
            sX[row * 64 + c + 1] = __float2half_rn(v.y);
            sX[row * 64 + c + 2] = __float2half_rn(v.z);
            sX[row * 64 + c + 3] = __float2half_rn(v.w);
        }
    }
    __syncthreads();

    // phase 2: wmma. warp w: strip = w/2 (16 rows), colbase = (w&1)*64.
    int w = tid >> 5;
    int strip = w >> 1;
    int colbase = (w & 1) * 64;

    wmma::fragment<wmma::accumulator, 16, 16, 16, float> acc[4];
#pragma unroll
    for (int t = 0; t < 4; t++) wmma::fill_fragment(acc[t], 0.f);

#pragma unroll
    for (int k = 0; k < 4; k++) {
        wmma::fragment<wmma::matrix_a, 16, 16, 16, __half, wmma::row_major> a;
        wmma::load_matrix_sync(a, sX + strip * 16 * 64 + k * 16, 64);
#pragma unroll
        for (int t = 0; t < 4; t++) {
            wmma::fragment<wmma::matrix_b, 16, 16, 16, __half, wmma::row_major> b;
            wmma::load_matrix_sync(b, sW + k * 16 * 128 + colbase + t * 16, 128);
            wmma::mma_sync(acc[t], a, b, acc[t]);
        }
    }
    __syncthreads();  // all mma reads of sW/sX done before staging overwrites

    // phase 3: stage fp32 results
#pragma unroll
    for (int t = 0; t < 4; t++)
        wmma::store_matrix_sync(sOut + strip * 16 * 128 + colbase + t * 16, acc[t], 128,
                                wmma::mem_row_major);
    __syncthreads();

    // phase 4: epilogue — xl fp16, xr fp32 + b1 (vectorized)
    for (int i = tid; i < 64 * 16; i += 256) {
        int row = i >> 4;
        int q   = i & 15;       // 4-feature chunk
        int gi  = base + row;
        if (gi >= n) continue;
        int j = q * 4;
        float l0 = sOut[row * 128 + j + 0];
        float l1 = sOut[row * 128 + j + 1];
        float l2 = sOut[row * 128 + j + 2];
        float l3 = sOut[row * 128 + j + 3];
        float r0 = sOut[row * 128 + 64 + j + 0] + sb[j + 0];
        float r1 = sOut[row * 128 + 64 + j + 1] + sb[j + 1];
        float r2 = sOut[row * 128 + 64 + j + 2] + sb[j + 2];
        float r3 = sOut[row * 128 + 64 + j + 3] + sb[j + 3];
        __half2 h01 = __floats2half2_rn(l0, l1);
        __half2 h23 = __floats2half2_rn(l2, l3);
        uint2 hv;
        hv.x = *reinterpret_cast<unsigned*>(&h01);
        hv.y = *reinterpret_cast<unsigned*>(&h23);
        reinterpret_cast<uint2*>(xl + (size_t)gi * D)[q] = hv;
        reinterpret_cast<float4*>(xr + (size_t)gi * D)[q] = make_float4(r0, r1, r2, r3);
    }
}

// ---------------- agg64_fused (verbatim R12/passing) ----------------
__global__ void agg64_fused_kernel(const __half* __restrict__ xl, const float* __restrict__ xr,
                                   float* __restrict__ h, int n) {
    int node = blockIdx.x * 8 + (threadIdx.x >> 5);
    if (node >= n) return;
    int lane = threadIdx.x & 31;
    int hf   = lane >> 4;
    int sub  = lane & 15;

    int rs  = g_start[node];
    int deg = g_deg[node];
    const uint2* f = reinterpret_cast<const uint2*>(xl);

    float4 acc = make_float4(0.f, 0.f, 0.f, 0.f);
    for (int base = 0; base < deg; base += 32) {
        int m = min(32, deg - base);
        int c = (lane < m) ? __ldg(&g_col[rs + base + lane]) : 0;
#pragma unroll 4
        for (int q = 0; q < m; q += 2) {
            int e = q + hf;
            int idx = __shfl_sync(0xffffffffu, c, e);
            uint2 v = __ldg(&f[(size_t)idx * 16 + sub]);
            float2 a = __half22float2(*reinterpret_cast<__half2*>(&v.x));
            float2 b = __half22float2(*reinterpret_cast<__half2*>(&v.y));
            if (e < m) {
                acc.x += a.x; acc.y += a.y; acc.z += b.x; acc.w += b.y;
            }
        }
    }
    acc.x += __shfl_xor_sync(0xffffffffu, acc.x, 16);
    acc.y += __shfl_xor_sync(0xffffffffu, acc.y, 16);
    acc.z += __shfl_xor_sync(0xffffffffu, acc.z, 16);
    acc.w += __shfl_xor_sync(0xffffffffu, acc.w, 16);

    if (hf == 0) {
        float inv = 1.f / fmaxf((float)deg, 1.f);
        const float4* xr4 = reinterpret_cast<const float4*>(xr);
        float4 r = __ldg(&xr4[(size_t)node * 16 + sub]);
        float4 hv;
        hv.x = fmaxf(acc.x * inv + r.x, 0.f);
        hv.y = fmaxf(acc.y * inv + r.y, 0.f);
        hv.z = fmaxf(acc.z * inv + r.z, 0.f);
        hv.w = fmaxf(acc.w * inv + r.w, 0.f);
        reinterpret_cast<float4*>(h)[(size_t)node * 16 + sub] = hv;
    }
}

// ---------------- dense12 (verbatim R12/passing) ----------------
__global__ void dense12_kernel(const float* __restrict__ h, const float* __restrict__ W2l,
                               const float* __restrict__ W2r, const float* __restrict__ b2,
                               __half* __restrict__ hl, float* __restrict__ hr, int n) {
    __shared__ float sWl[D * H2];
    __shared__ float sWr[D * H2];
    __shared__ float sb[H2];
    int tid = threadIdx.x;
    for (int i = tid; i < D * H2; i += 256) { sWl[i] = W2l[i]; sWr[i] = W2r[i]; }
    if (tid < H2) sb[tid] = b2[tid];
    __syncthreads();

    int j  = tid & 15;
    int il = tid >> 4;
    int base = blockIdx.x * 64;

    for (int s = 0; s < 64; s += 16) {
        int i = base + il + s;
        if (i >= n) continue;
        const float4* h4 = reinterpret_cast<const float4*>(h + (size_t)i * D);
        float al = 0.f, ar = sb[j];
#pragma unroll
        for (int k4 = 0; k4 < 16; k4++) {
            float4 hv = h4[k4];
            int k = k4 * 4;
            al += hv.x * sWl[(k + 0) * H2 + j] + hv.y * sWl[(k + 1) * H2 + j]
                + hv.z * sWl[(k + 2) * H2 + j] + hv.w * sWl[(k + 3) * H2 + j];
            ar += hv.x * sWr[(k + 0) * H2 + j] + hv.y * sWr[(k + 1) * H2 + j]
                + hv.z * sWr[(k + 2) * H2 + j] + hv.w * sWr[(k + 3) * H2 + j];
        }
        hl[(size_t)i * H2 + j] = __float2half_rn(al);
        hr[(size_t)i * H2 + j] = ar;
    }
}

// ---------------- agg16_final (verbatim R12/passing) ----------------
__global__ void agg16_final_kernel(const __half* __restrict__ hl, const float* __restrict__ hr,
                                   const float* __restrict__ Wfc, const float* __restrict__ bfc,
                                   float* __restrict__ out, int n) {
    int node = blockIdx.x * 8 + (threadIdx.x >> 5);
    if (node >= n) return;
    int lane = threadIdx.x & 31;
    int grp = lane >> 2;
    int sub = lane & 3;

    int rs  = g_start[node];
    int deg = g_deg[node];
    const uint2* f = reinterpret_cast<const uint2*>(hl);

    float4 acc = make_float4(0.f, 0.f, 0.f, 0.f);
    for (int base = 0; base < deg; base += 32) {
        int m = min(32, deg - base);
        int c = (lane < m) ? __ldg(&g_col[rs + base + lane]) : 0;
#pragma unroll 4
        for (int q = 0; q < m; q += 8) {
            int e = q + grp;
            int idx = __shfl_sync(0xffffffffu, c, e);
            uint2 v = __ldg(&f[(size_t)idx * 4 + sub]);
            float2 a = __half22float2(*reinterpret_cast<__half2*>(&v.x));
            float2 b = __half22float2(*reinterpret_cast<__half2*>(&v.y));
            if (e < m) {
                acc.x += a.x; acc.y += a.y; acc.z += b.x; acc.w += b.y;
            }
        }
    }
    acc.x += __shfl_xor_sync(0xffffffffu, acc.x, 4);
    acc.y += __shfl_xor_sync(0xffffffffu, acc.y, 4);
    acc.z += __shfl_xor_sync(0xffffffffu, acc.z, 4);
    acc.w += __shfl_xor_sync(0xffffffffu, acc.w, 4);
    acc.x += __shfl_xor_sync(0xffffffffu, acc.x, 8);
    acc.y += __shfl_xor_sync(0xffffffffu, acc.y, 8);
    acc.z += __shfl_xor_sync(0xffffffffu, acc.z, 8);
    acc.w += __shfl_xor_sync(0xffffffffu, acc.w, 8);
    acc.x += __shfl_xor_sync(0xffffffffu, acc.x, 16);
    acc.y += __shfl_xor_sync(0xffffffffu, acc.y, 16);
    acc.z += __shfl_xor_sync(0xffffffffu, acc.z, 16);
    acc.w += __shfl_xor_sync(0xffffffffu, acc.w, 16);

    float inv = 1.f / fmaxf((float)deg, 1.f);
    const float4* hr4 = reinterpret_cast<const float4*>(hr);
    float4 r = __ldg(&hr4[(size_t)node * 4 + sub]);
    float a0 = acc.x * inv + r.x;
    float a1 = acc.y * inv + r.y;
    float a2 = acc.z * inv + r.z;
    float a3 = acc.w * inv + r.w;

    int jb = sub * 4;
    float o0 = a0 * __ldg(&Wfc[(jb + 0) * OUTW + 0]) + a1 * __ldg(&Wfc[(jb + 1) * OUTW + 0])
             + a2 * __ldg(&Wfc[(jb + 2) * OUTW + 0]) + a3 * __ldg(&Wfc[(jb + 3) * OUTW + 0]);
    float o1 = a0 * __ldg(&Wfc[(jb + 0) * OUTW + 1]) + a1 * __ldg(&Wfc[(jb + 1) * OUTW + 1])
             + a2 * __ldg(&Wfc[(jb + 2) * OUTW + 1]) + a3 * __ldg(&Wfc[(jb + 3) * OUTW + 1]);
    o0 += __shfl_xor_sync(0xffffffffu, o0, 1);
    o1 += __shfl_xor_sync(0xffffffffu, o1, 1);
    o0 += __shfl_xor_sync(0xffffffffu, o0, 2);
    o1 += __shfl_xor_sync(0xffffffffu, o1, 2);

    if (lane == 0) {
        out[(size_t)node * OUTW + 0] = o0 + __ldg(&bfc[0]);
        out[(size_t)node * OUTW + 1] = o1 + __ldg(&bfc[1]);
    }
}

// ---------------- launcher (single stream, kernels only) ----------------
extern "C" void kernel_launch(void* const* d_in, const int* in_sizes, int n_in,
                              void* d_out, int out_size) {
    const float* x   = (const float*)d_in[0];
    const int*   e   = (const int*)d_in[1];
    const float* W1l = (const float*)d_in[2];
    const float* b1  = (const float*)d_in[3];
    const float* W1r = (const float*)d_in[4];
    const float* W2l = (const float*)d_in[5];
    const float* b2  = (const float*)d_in[6];
    const float* W2r = (const float*)d_in[7];
    const float* Wfc = (const float*)d_in[8];
    const float* bfc = (const float*)d_in[9];
    float* out = (float*)d_out;

    int n = in_sizes[0] / D;
    int E = in_sizes[1] / 2;
    const int* src = e;
    const int* dst = e + E;

    __half *xlp, *hlp;
    float *xrp, *hp, *hrp;
    cudaGetSymbolAddress((void**)&xlp, g_xl);
    cudaGetSymbolAddress((void**)&xrp, g_xr);
    cudaGetSymbolAddress((void**)&hp, g_h);
    cudaGetSymbolAddress((void**)&hlp, g_hl);
    cudaGetSymbolAddress((void**)&hrp, g_hr);

    // dense0 (tensor cores) + zero prologue (grid*256 >= n)
    int dense0Blocks = (n + 63) / 64;
    dense0z_kernel<<<dense0Blocks, 256>>>(x, W1l, W1r, b1, xlp, xrp, n);

    // CSR build
    hist_kernel<<<(E / 8 + 255) / 256, 256>>>(dst, E);
    alloc_kernel<<<(n + 255) / 256, 256>>>(n);
    fill_kernel<<<(E / 8 + 255) / 256, 256>>>(src, dst, E);

    // layer 1 aggregate
    agg64_fused_kernel<<<(n + 7) / 8, 256>>>(xlp, xrp, hp, n);

    // layer 2 + fc (fused tail)
    dense12_kernel<<<(n + 63) / 64, 256>>>(hp, W2l, W2r, b2, hlp, hrp, n);
    agg16_final_kernel<<<(n + 7) / 8, 256>>>(hlp, hrp, Wfc, bfc, out, n);
}

// round 14
// speedup vs baseline: 1.2074x; 1.0153x over previous
#include <cuda_runtime.h>
#include <cuda_bf16.h>
#include <cuda_fp16.h>
#include <mma.h>

using namespace nvcuda;

constexpr int MAXN = 50000;
constexpr int MAXE = 1250000;
constexpr int D    = 64;
constexpr int H2   = 16;
constexpr int OUTW = 2;

// ---------------- device scratch ----------------
__device__ int    g_deg[MAXN];
__device__ int    g_start[MAXN];
__device__ int    g_rank[MAXE];
__device__ int    g_col[MAXE];
__device__ int    g_counter;
__device__ __half g_xl[(size_t)MAXN * D];
__device__ float  g_xr[(size_t)MAXN * D];
__device__ float  g_h[(size_t)MAXN * D];
__device__ __half g_hl[(size_t)MAXN * H2];
__device__ float  g_hr[(size_t)MAXN * H2];

// ---------------- hist (R13 body + PDL: prefetch inputs, sync before atomics) ----------------
__global__ void hist_kernel(const int* __restrict__ dst, int E) {
    int i = (blockIdx.x * blockDim.x + threadIdx.x) * 8;
    if (i + 7 < E) {
        int4 d0 = *reinterpret_cast<const int4*>(dst + i);
        int4 d1 = *reinterpret_cast<const int4*>(dst + i + 4);
        cudaGridDependencySynchronize();   // wait: g_deg zeroed by dense0z
        int4 r0, r1;
        r0.x = atomicAdd(&g_deg[d0.x], 1);
        r0.y = atomicAdd(&g_deg[d0.y], 1);
        r0.z = atomicAdd(&g_deg[d0.z], 1);
        r0.w = atomicAdd(&g_deg[d0.w], 1);
        r1.x = atomicAdd(&g_deg[d1.x], 1);
        r1.y = atomicAdd(&g_deg[d1.y], 1);
        r1.z = atomicAdd(&g_deg[d1.z], 1);
        r1.w = atomicAdd(&g_deg[d1.w], 1);
        *reinterpret_cast<int4*>(g_rank + i)     = r0;
        *reinterpret_cast<int4*>(g_rank + i + 4) = r1;
    } else {
        cudaGridDependencySynchronize();
        for (int k = i; k < E; k++) g_rank[k] = atomicAdd(&g_deg[dst[k]], 1);
    }
}

__global__ void alloc_kernel(int n) {
    cudaGridDependencySynchronize();       // wait: g_deg complete (hist)
    int i = blockIdx.x * blockDim.x + threadIdx.x;
    int lane = threadIdx.x & 31;
    int deg = (i < n) ? g_deg[i] : 0;
    int incl = deg;
#pragma unroll
    for (int off = 1; off < 32; off <<= 1) {
        int v = __shfl_up_sync(0xffffffffu, incl, off);
        if (lane >= off) incl += v;
    }
    int excl = incl - deg;
    int base = 0;
    if (lane == 31) base = atomicAdd(&g_counter, incl);
    base = __shfl_sync(0xffffffffu, base, 31);
    if (i < n) g_start[i] = base + excl;
}

__global__ void fill_kernel(const int* __restrict__ src, const int* __restrict__ dst, int E) {
    int i = (blockIdx.x * blockDim.x + threadIdx.x) * 8;
    if (i + 7 < E) {
        // prefetch harness inputs before the dependency sync
        int4 s0 = *reinterpret_cast<const int4*>(src + i);
        int4 s1 = *reinterpret_cast<const int4*>(src + i + 4);
        int4 d0 = *reinterpret_cast<const int4*>(dst + i);
        int4 d1 = *reinterpret_cast<const int4*>(dst + i + 4);
        cudaGridDependencySynchronize();   // wait: g_start (alloc; transitively g_rank)
        int4 r0 = *reinterpret_cast<const int4*>(g_rank + i);
        int4 r1 = *reinterpret_cast<const int4*>(g_rank + i + 4);
        g_col[__ldg(&g_start[d0.x]) + r0.x] = s0.x;
        g_col[__ldg(&g_start[d0.y]) + r0.y] = s0.y;
        g_col[__ldg(&g_start[d0.z]) + r0.z] = s0.z;
        g_col[__ldg(&g_start[d0.w]) + r0.w] = s0.w;
        g_col[__ldg(&g_start[d1.x]) + r1.x] = s1.x;
        g_col[__ldg(&g_start[d1.y]) + r1.y] = s1.y;
        g_col[__ldg(&g_start[d1.z]) + r1.z] = s1.z;
        g_col[__ldg(&g_start[d1.w]) + r1.w] = s1.w;
    } else {
        cudaGridDependencySynchronize();
        for (int k = i; k < E; k++)
            g_col[__ldg(&g_start[dst[k]]) + g_rank[k]] = src[k];
    }
}

// ---------------- dense0z (verbatim R13; first kernel, no sync) ----------------
__global__ void dense0z_kernel(const float* __restrict__ x, const float* __restrict__ W1l,
                               const float* __restrict__ W1r, const float* __restrict__ b1,
                               __half* __restrict__ xl, float* __restrict__ xr, int n) {
    {
        int zi = blockIdx.x * 256 + threadIdx.x;
        if (zi < n) g_deg[zi] = 0;
        if (zi == 0) g_counter = 0;
    }

    __shared__ float sOut[64 * 128];
    __shared__ float sb[D];
    __half* sW = reinterpret_cast<__half*>(sOut);
    __half* sX = reinterpret_cast<__half*>(sOut + 4096);

    int tid = threadIdx.x;
    int base = blockIdx.x * 64;

    for (int i = tid; i < D * D; i += 256) {
        int k = i >> 6, j = i & 63;
        sW[k * 128 + j]      = __float2half_rn(W1l[i]);
        sW[k * 128 + 64 + j] = __float2half_rn(W1r[i]);
    }
    if (tid < D) sb[tid] = b1[tid];

    {
        int row  = tid >> 2;
        int col0 = (tid & 3) * 16;
        int gr = min(base + row, n - 1);
        const float4* xp = reinterpret_cast<const float4*>(x + (size_t)gr * D + col0);
#pragma unroll
        for (int q = 0; q < 4; q++) {
            float4 v = __ldg(&xp[q]);
            int c = col0 + q * 4;
            sX[row * 64 + c + 0] = __float2half_rn(v.x);
            sX[row * 64 + c + 1] = __float2half_rn(v.y);
            sX[row * 64 + c + 2] = __float2half_rn(v.z);
            sX[row * 64 + c + 3] = __float2half_rn(v.w);
        }
    }
    __syncthreads();

    int w = tid >> 5;
    int strip = w >> 1;
    int colbase = (w & 1) * 64;

    wmma::fragment<wmma::accumulator, 16, 16, 16, float> acc[4];
#pragma unroll
    for (int t = 0; t < 4; t++) wmma::fill_fragment(acc[t], 0.f);

#pragma unroll
    for (int k = 0; k < 4; k++) {
        wmma::fragment<wmma::matrix_a, 16, 16, 16, __half, wmma::row_major> a;
        wmma::load_matrix_sync(a, sX + strip * 16 * 64 + k * 16, 64);
#pragma unroll
        for (int t = 0; t < 4; t++) {
            wmma::fragment<wmma::matrix_b, 16, 16, 16, __half, wmma::row_major> b;
            wmma::load_matrix_sync(b, sW + k * 16 * 128 + colbase + t * 16, 128);
            wmma::mma_sync(acc[t], a, b, acc[t]);
        }
    }
    __syncthreads();

#pragma unroll
    for (int t = 0; t < 4; t++)
        wmma::store_matrix_sync(sOut + strip * 16 * 128 + colbase + t * 16, acc[t], 128,
                                wmma::mem_row_major);
    __syncthreads();

    for (int i = tid; i < 64 * 16; i += 256) {
        int row = i >> 4;
        int q   = i & 15;
        int gi  = base + row;
        if (gi >= n) continue;
        int j = q * 4;
        float l0 = sOut[row * 128 + j + 0];
        float l1 = sOut[row * 128 + j + 1];
        float l2 = sOut[row * 128 + j + 2];
        float l3 = sOut[row * 128 + j + 3];
        float r0 = sOut[row * 128 + 64 + j + 0] + sb[j + 0];
        float r1 = sOut[row * 128 + 64 + j + 1] + sb[j + 1];
        float r2 = sOut[row * 128 + 64 + j + 2] + sb[j + 2];
        float r3 = sOut[row * 128 + 64 + j + 3] + sb[j + 3];
        __half2 h01 = __floats2half2_rn(l0, l1);
        __half2 h23 = __floats2half2_rn(l2, l3);
        uint2 hv;
        hv.x = *reinterpret_cast<unsigned*>(&h01);
        hv.y = *reinterpret_cast<unsigned*>(&h23);
        reinterpret_cast<uint2*>(xl + (size_t)gi * D)[q] = hv;
        reinterpret_cast<float4*>(xr + (size_t)gi * D)[q] = make_float4(r0, r1, r2, r3);
    }
}

// ---------------- agg64_fused (R13 body + entry sync) ----------------
__global__ void agg64_fused_kernel(const __half* __restrict__ xl, const float* __restrict__ xr,
                                   float* __restrict__ h, int n) {
    int node = blockIdx.x * 8 + (threadIdx.x >> 5);
    int lane = threadIdx.x & 31;
    int hf   = lane >> 4;
    int sub  = lane & 15;
    cudaGridDependencySynchronize();       // wait: g_col (fill; transitively all CSR + xl/xr)
    if (node >= n) return;

    int rs  = g_start[node];
    int deg = g_deg[node];
    const uint2* f = reinterpret_cast<const uint2*>(xl);

    float4 acc = make_float4(0.f, 0.f, 0.f, 0.f);
    for (int base = 0; base < deg; base += 32) {
        int m = min(32, deg - base);
        int c = (lane < m) ? __ldg(&g_col[rs + base + lane]) : 0;
#pragma unroll 4
        for (int q = 0; q < m; q += 2) {
            int e = q + hf;
            int idx = __shfl_sync(0xffffffffu, c, e);
            uint2 v = __ldg(&f[(size_t)idx * 16 + sub]);
            float2 a = __half22float2(*reinterpret_cast<__half2*>(&v.x));
            float2 b = __half22float2(*reinterpret_cast<__half2*>(&v.y));
            if (e < m) {
                acc.x += a.x; acc.y += a.y; acc.z += b.x; acc.w += b.y;
            }
        }
    }
    acc.x += __shfl_xor_sync(0xffffffffu, acc.x, 16);
    acc.y += __shfl_xor_sync(0xffffffffu, acc.y, 16);
    acc.z += __shfl_xor_sync(0xffffffffu, acc.z, 16);
    acc.w += __shfl_xor_sync(0xffffffffu, acc.w, 16);

    if (hf == 0) {
        float inv = 1.f / fmaxf((float)deg, 1.f);
        const float4* xr4 = reinterpret_cast<const float4*>(xr);
        float4 r = __ldg(&xr4[(size_t)node * 16 + sub]);
        float4 hv;
        hv.x = fmaxf(acc.x * inv + r.x, 0.f);
        hv.y = fmaxf(acc.y * inv + r.y, 0.f);
        hv.z = fmaxf(acc.z * inv + r.z, 0.f);
        hv.w = fmaxf(acc.w * inv + r.w, 0.f);
        reinterpret_cast<float4*>(h)[(size_t)node * 16 + sub] = hv;
    }
}

// ---------------- dense12 (R13 body + weight prologue before sync) ----------------
__global__ void dense12_kernel(const float* __restrict__ h, const float* __restrict__ W2l,
                               const float* __restrict__ W2r, const float* __restrict__ b2,
                               __half* __restrict__ hl, float* __restrict__ hr, int n) {
    __shared__ float sWl[D * H2];
    __shared__ float sWr[D * H2];
    __shared__ float sb[H2];
    int tid = threadIdx.x;
    for (int i = tid; i < D * H2; i += 256) { sWl[i] = W2l[i]; sWr[i] = W2r[i]; }
    if (tid < H2) sb[tid] = b2[tid];
    __syncthreads();
    cudaGridDependencySynchronize();       // wait: h (agg64_fused)

    int j  = tid & 15;
    int il = tid >> 4;
    int base = blockIdx.x * 64;

    for (int s = 0; s < 64; s += 16) {
        int i = base + il + s;
        if (i >= n) continue;
        const float4* h4 = reinterpret_cast<const float4*>(h + (size_t)i * D);
        float al = 0.f, ar = sb[j];
#pragma unroll
        for (int k4 = 0; k4 < 16; k4++) {
            float4 hv = h4[k4];
            int k = k4 * 4;
            al += hv.x * sWl[(k + 0) * H2 + j] + hv.y * sWl[(k + 1) * H2 + j]
                + hv.z * sWl[(k + 2) * H2 + j] + hv.w * sWl[(k + 3) * H2 + j];
            ar += hv.x * sWr[(k + 0) * H2 + j] + hv.y * sWr[(k + 1) * H2 + j]
                + hv.z * sWr[(k + 2) * H2 + j] + hv.w * sWr[(k + 3) * H2 + j];
        }
        hl[(size_t)i * H2 + j] = __float2half_rn(al);
        hr[(size_t)i * H2 + j] = ar;
    }
}

// ---------------- agg16_final (R13 body + entry sync) ----------------
__global__ void agg16_final_kernel(const __half* __restrict__ hl, const float* __restrict__ hr,
                                   const float* __restrict__ Wfc, const float* __restrict__ bfc,
                                   float* __restrict__ out, int n) {
    int node = blockIdx.x * 8 + (threadIdx.x >> 5);
    int lane = threadIdx.x & 31;
    int grp = lane >> 2;
    int sub = lane & 3;
    cudaGridDependencySynchronize();       // wait: hl/hr (dense12)
    if (node >= n) return;

    int rs  = g_start[node];
    int deg = g_deg[node];
    const uint2* f = reinterpret_cast<const uint2*>(hl);

    float4 acc = make_float4(0.f, 0.f, 0.f, 0.f);
    for (int base = 0; base < deg; base += 32) {
        int m = min(32, deg - base);
        int c = (lane < m) ? __ldg(&g_col[rs + base + lane]) : 0;
#pragma unroll 4
        for (int q = 0; q < m; q += 8) {
            int e = q + grp;
            int idx = __shfl_sync(0xffffffffu, c, e);
            uint2 v = __ldg(&f[(size_t)idx * 4 + sub]);
            float2 a = __half22float2(*reinterpret_cast<__half2*>(&v.x));
            float2 b = __half22float2(*reinterpret_cast<__half2*>(&v.y));
            if (e < m) {
                acc.x += a.x; acc.y += a.y; acc.z += b.x; acc.w += b.y;
            }
        }
    }
    acc.x += __shfl_xor_sync(0xffffffffu, acc.x, 4);
    acc.y += __shfl_xor_sync(0xffffffffu, acc.y, 4);
    acc.z += __shfl_xor_sync(0xffffffffu, acc.z, 4);
    acc.w += __shfl_xor_sync(0xffffffffu, acc.w, 4);
    acc.x += __shfl_xor_sync(0xffffffffu, acc.x, 8);
    acc.y += __shfl_xor_sync(0xffffffffu, acc.y, 8);
    acc.z += __shfl_xor_sync(0xffffffffu, acc.z, 8);
    acc.w += __shfl_xor_sync(0xffffffffu, acc.w, 8);
    acc.x += __shfl_xor_sync(0xffffffffu, acc.x, 16);
    acc.y += __shfl_xor_sync(0xffffffffu, acc.y, 16);
    acc.z += __shfl_xor_sync(0xffffffffu, acc.z, 16);
    acc.w += __shfl_xor_sync(0xffffffffu, acc.w, 16);

    float inv = 1.f / fmaxf((float)deg, 1.f);
    const float4* hr4 = reinterpret_cast<const float4*>(hr);
    float4 r = __ldg(&hr4[(size_t)node * 4 + sub]);
    float a0 = acc.x * inv + r.x;
    float a1 = acc.y * inv + r.y;
    float a2 = acc.z * inv + r.z;
    float a3 = acc.w * inv + r.w;

    int jb = sub * 4;
    float o0 = a0 * __ldg(&Wfc[(jb + 0) * OUTW + 0]) + a1 * __ldg(&Wfc[(jb + 1) * OUTW + 0])
             + a2 * __ldg(&Wfc[(jb + 2) * OUTW + 0]) + a3 * __ldg(&Wfc[(jb + 3) * OUTW + 0]);
    float o1 = a0 * __ldg(&Wfc[(jb + 0) * OUTW + 1]) + a1 * __ldg(&Wfc[(jb + 1) * OUTW + 1])
             + a2 * __ldg(&Wfc[(jb + 2) * OUTW + 1]) + a3 * __ldg(&Wfc[(jb + 3) * OUTW + 1]);
    o0 += __shfl_xor_sync(0xffffffffu, o0, 1);
    o1 += __shfl_xor_sync(0xffffffffu, o1, 1);
    o0 += __shfl_xor_sync(0xffffffffu, o0, 2);
    o1 += __shfl_xor_sync(0xffffffffu, o1, 2);

    if (lane == 0) {
        out[(size_t)node * OUTW + 0] = o0 + __ldg(&bfc[0]);
        out[(size_t)node * OUTW + 1] = o1 + __ldg(&bfc[1]);
    }
}

// ---------------- launcher (single stream; PDL-chained launches) ----------------
template <typename... Args>
static void launch_pdl(void (*kernel)(Args...), int grid, Args... args) {
    cudaLaunchConfig_t cfg = {};
    cfg.gridDim  = dim3((unsigned)grid, 1, 1);
    cfg.blockDim = dim3(256, 1, 1);
    cfg.stream   = 0;
    cudaLaunchAttribute attr[1];
    attr[0].id = cudaLaunchAttributeProgrammaticStreamSerialization;
    attr[0].val.programmaticStreamSerializationAllowed = 1;
    cfg.attrs = attr;
    cfg.numAttrs = 1;
    cudaLaunchKernelEx(&cfg, kernel, args...);
}

extern "C" void kernel_launch(void* const* d_in, const int* in_sizes, int n_in,
                              void* d_out, int out_size) {
    const float* x   = (const float*)d_in[0];
    const int*   e   = (const int*)d_in[1];
    const float* W1l = (const float*)d_in[2];
    const float* b1  = (const float*)d_in[3];
    const float* W1r = (const float*)d_in[4];
    const float* W2l = (const float*)d_in[5];
    const float* b2  = (const float*)d_in[6];
    const float* W2r = (const float*)d_in[7];
    const float* Wfc = (const float*)d_in[8];
    const float* bfc = (const float*)d_in[9];
    float* out = (float*)d_out;

    int n = in_sizes[0] / D;
    int E = in_sizes[1] / 2;
    const int* src = e;
    const int* dst = e + E;

    __half *xlp, *hlp;
    float *xrp, *hp, *hrp;
    cudaGetSymbolAddress((void**)&xlp, g_xl);
    cudaGetSymbolAddress((void**)&xrp, g_xr);
    cudaGetSymbolAddress((void**)&hp, g_h);
    cudaGetSymbolAddress((void**)&hlp, g_hl);
    cudaGetSymbolAddress((void**)&hrp, g_hr);

    int dense0Blocks = (n + 63) / 64;
    int edgeBlocks   = (E / 8 + 255) / 256;

    // first kernel: normal launch
    dense0z_kernel<<<dense0Blocks, 256>>>(x, W1l, W1r, b1, xlp, xrp, n);

    // PDL chain: each kernel gridDepSyncs before consuming upstream data
    launch_pdl(hist_kernel, edgeBlocks, dst, E);
    launch_pdl(alloc_kernel, (n + 255) / 256, n);
    launch_pdl(fill_kernel, edgeBlocks, src, dst, E);
    launch_pdl(agg64_fused_kernel, (n + 7) / 8,
               (const __half*)xlp, (const float*)xrp, hp, n);
    launch_pdl(dense12_kernel, (n + 63) / 64,
               (const float*)hp, W2l, W2r, b2, hlp, hrp, n);
    launch_pdl(agg16_final_kernel, (n + 7) / 8,
               (const __half*)hlp, (const float*)hrp, Wfc, bfc, out, n);
}

// round 15
// speedup vs baseline: 1.2625x; 1.0456x over previous
#include <cuda_runtime.h>
#include <cuda_bf16.h>
#include <cuda_fp16.h>
#include <mma.h>

using namespace nvcuda;

constexpr int MAXN = 50000;
constexpr int MAXE = 1250000;
constexpr int D    = 64;
constexpr int H2   = 16;
constexpr int OUTW = 2;

// ---------------- device scratch ----------------
__device__ int    g_deg[MAXN];
__device__ int    g_start[MAXN];
__device__ int    g_rank[MAXE];
__device__ int    g_col[MAXE];
__device__ int    g_counter;
__device__ __half g_xl[(size_t)MAXN * D];
__device__ float  g_xr[(size_t)MAXN * D];
__device__ __half g_hl[(size_t)MAXN * H2];
__device__ float  g_hr[(size_t)MAXN * H2];

// ---------------- hist (verbatim R14/passing) ----------------
__global__ void hist_kernel(const int* __restrict__ dst, int E) {
    int i = (blockIdx.x * blockDim.x + threadIdx.x) * 8;
    if (i + 7 < E) {
        int4 d0 = *reinterpret_cast<const int4*>(dst + i);
        int4 d1 = *reinterpret_cast<const int4*>(dst + i + 4);
        cudaGridDependencySynchronize();
        int4 r0, r1;
        r0.x = atomicAdd(&g_deg[d0.x], 1);
        r0.y = atomicAdd(&g_deg[d0.y], 1);
        r0.z = atomicAdd(&g_deg[d0.z], 1);
        r0.w = atomicAdd(&g_deg[d0.w], 1);
        r1.x = atomicAdd(&g_deg[d1.x], 1);
        r1.y = atomicAdd(&g_deg[d1.y], 1);
        r1.z = atomicAdd(&g_deg[d1.z], 1);
        r1.w = atomicAdd(&g_deg[d1.w], 1);
        *reinterpret_cast<int4*>(g_rank + i)     = r0;
        *reinterpret_cast<int4*>(g_rank + i + 4) = r1;
    } else {
        cudaGridDependencySynchronize();
        for (int k = i; k < E; k++) g_rank[k] = atomicAdd(&g_deg[dst[k]], 1);
    }
}

__global__ void alloc_kernel(int n) {
    cudaGridDependencySynchronize();
    int i = blockIdx.x * blockDim.x + threadIdx.x;
    int lane = threadIdx.x & 31;
    int deg = (i < n) ? g_deg[i] : 0;
    int incl = deg;
#pragma unroll
    for (int off = 1; off < 32; off <<= 1) {
        int v = __shfl_up_sync(0xffffffffu, incl, off);
        if (lane >= off) incl += v;
    }
    int excl = incl - deg;
    int base = 0;
    if (lane == 31) base = atomicAdd(&g_counter, incl);
    base = __shfl_sync(0xffffffffu, base, 31);
    if (i < n) g_start[i] = base + excl;
}

__global__ void fill_kernel(const int* __restrict__ src, const int* __restrict__ dst, int E) {
    int i = (blockIdx.x * blockDim.x + threadIdx.x) * 8;
    if (i + 7 < E) {
        int4 s0 = *reinterpret_cast<const int4*>(src + i);
        int4 s1 = *reinterpret_cast<const int4*>(src + i + 4);
        int4 d0 = *reinterpret_cast<const int4*>(dst + i);
        int4 d1 = *reinterpret_cast<const int4*>(dst + i + 4);
        cudaGridDependencySynchronize();
        int4 r0 = *reinterpret_cast<const int4*>(g_rank + i);
        int4 r1 = *reinterpret_cast<const int4*>(g_rank + i + 4);
        g_col[__ldg(&g_start[d0.x]) + r0.x] = s0.x;
        g_col[__ldg(&g_start[d0.y]) + r0.y] = s0.y;
        g_col[__ldg(&g_start[d0.z]) + r0.z] = s0.z;
        g_col[__ldg(&g_start[d0.w]) + r0.w] = s0.w;
        g_col[__ldg(&g_start[d1.x]) + r1.x] = s1.x;
        g_col[__ldg(&g_start[d1.y]) + r1.y] = s1.y;
        g_col[__ldg(&g_start[d1.z]) + r1.z] = s1.z;
        g_col[__ldg(&g_start[d1.w]) + r1.w] = s1.w;
    } else {
        cudaGridDependencySynchronize();
        for (int k = i; k < E; k++)
            g_col[__ldg(&g_start[dst[k]]) + g_rank[k]] = src[k];
    }
}

// ---------------- dense0z (verbatim R14/passing) ----------------
__global__ void dense0z_kernel(const float* __restrict__ x, const float* __restrict__ W1l,
                               const float* __restrict__ W1r, const float* __restrict__ b1,
                               __half* __restrict__ xl, float* __restrict__ xr, int n) {
    {
        int zi = blockIdx.x * 256 + threadIdx.x;
        if (zi < n) g_deg[zi] = 0;
        if (zi == 0) g_counter = 0;
    }

    __shared__ float sOut[64 * 128];
    __shared__ float sb[D];
    __half* sW = reinterpret_cast<__half*>(sOut);
    __half* sX = reinterpret_cast<__half*>(sOut + 4096);

    int tid = threadIdx.x;
    int base = blockIdx.x * 64;

    for (int i = tid; i < D * D; i += 256) {
        int k = i >> 6, j = i & 63;
        sW[k * 128 + j]      = __float2half_rn(W1l[i]);
        sW[k * 128 + 64 + j] = __float2half_rn(W1r[i]);
    }
    if (tid < D) sb[tid] = b1[tid];

    {
        int row  = tid >> 2;
        int col0 = (tid & 3) * 16;
        int gr = min(base + row, n - 1);
        const float4* xp = reinterpret_cast<const float4*>(x + (size_t)gr * D + col0);
#pragma unroll
        for (int q = 0; q < 4; q++) {
            float4 v = __ldg(&xp[q]);
            int c = col0 + q * 4;
            sX[row * 64 + c + 0] = __float2half_rn(v.x);
            sX[row * 64 + c + 1] = __float2half_rn(v.y);
            sX[row * 64 + c + 2] = __float2half_rn(v.z);
            sX[row * 64 + c + 3] = __float2half_rn(v.w);
        }
    }
    __syncthreads();

    int w = tid >> 5;
    int strip = w >> 1;
    int colbase = (w & 1) * 64;

    wmma::fragment<wmma::accumulator, 16, 16, 16, float> acc[4];
#pragma unroll
    for (int t = 0; t < 4; t++) wmma::fill_fragment(acc[t], 0.f);

#pragma unroll
    for (int k = 0; k < 4; k++) {
        wmma::fragment<wmma::matrix_a, 16, 16, 16, __half, wmma::row_major> a;
        wmma::load_matrix_sync(a, sX + strip * 16 * 64 + k * 16, 64);
#pragma unroll
        for (int t = 0; t < 4; t++) {
            wmma::fragment<wmma::matrix_b, 16, 16, 16, __half, wmma::row_major> b;
            wmma::load_matrix_sync(b, sW + k * 16 * 128 + colbase + t * 16, 128);
            wmma::mma_sync(acc[t], a, b, acc[t]);
        }
    }
    __syncthreads();

#pragma unroll
    for (int t = 0; t < 4; t++)
        wmma::store_matrix_sync(sOut + strip * 16 * 128 + colbase + t * 16, acc[t], 128,
                                wmma::mem_row_major);
    __syncthreads();

    for (int i = tid; i < 64 * 16; i += 256) {
        int row = i >> 4;
        int q   = i & 15;
        int gi  = base + row;
        if (gi >= n) continue;
        int j = q * 4;
        float l0 = sOut[row * 128 + j + 0];
        float l1 = sOut[row * 128 + j + 1];
        float l2 = sOut[row * 128 + j + 2];
        float l3 = sOut[row * 128 + j + 3];
        float r0 = sOut[row * 128 + 64 + j + 0] + sb[j + 0];
        float r1 = sOut[row * 128 + 64 + j + 1] + sb[j + 1];
        float r2 = sOut[row * 128 + 64 + j + 2] + sb[j + 2];
        float r3 = sOut[row * 128 + 64 + j + 3] + sb[j + 3];
        __half2 h01 = __floats2half2_rn(l0, l1);
        __half2 h23 = __floats2half2_rn(l2, l3);
        uint2 hv;
        hv.x = *reinterpret_cast<unsigned*>(&h01);
        hv.y = *reinterpret_cast<unsigned*>(&h23);
        reinterpret_cast<uint2*>(xl + (size_t)gi * D)[q] = hv;
        reinterpret_cast<float4*>(xr + (size_t)gi * D)[q] = make_float4(r0, r1, r2, r3);
    }
}

// ---------------- agg64_dense12: gather + h-in-registers + layer2 GEMVs ----------------
// Gather loop verbatim R14. Epilogue: h row stays in warp registers; lane j<16
// computes hl_j, lane j>=16 computes hr_{j-16} via shfl-broadcast GEMV.
__global__ void agg64_dense12_kernel(const __half* __restrict__ xl, const float* __restrict__ xr,
                                     const float* __restrict__ W2l, const float* __restrict__ W2r,
                                     const float* __restrict__ b2,
                                     __half* __restrict__ hl, float* __restrict__ hr, int n) {
    __shared__ float sW2[64 * 32];   // [k][j]: j<16 = W2l, j>=16 = W2r
    __shared__ float sb2[H2];
    int tid = threadIdx.x;
    for (int i = tid; i < 64 * 16; i += 256) {
        int k = i >> 4, j = i & 15;
        sW2[k * 32 + j]      = W2l[k * H2 + j];
        sW2[k * 32 + 16 + j] = W2r[k * H2 + j];
    }
    if (tid < H2) sb2[tid] = b2[tid];
    __syncthreads();
    cudaGridDependencySynchronize();   // wait: g_col (fill) + xl/xr (dense0z)

    int node = blockIdx.x * 8 + (tid >> 5);
    if (node >= n) return;
    int lane = tid & 31;
    int hf   = lane >> 4;
    int sub  = lane & 15;

    int rs  = g_start[node];
    int deg = g_deg[node];
    const uint2* f = reinterpret_cast<const uint2*>(xl);

    float4 acc = make_float4(0.f, 0.f, 0.f, 0.f);
    for (int base = 0; base < deg; base += 32) {
        int m = min(32, deg - base);
        int c = (lane < m) ? __ldg(&g_col[rs + base + lane]) : 0;
#pragma unroll 4
        for (int q = 0; q < m; q += 2) {
            int e = q + hf;
            int idx = __shfl_sync(0xffffffffu, c, e);
            uint2 v = __ldg(&f[(size_t)idx * 16 + sub]);
            float2 a = __half22float2(*reinterpret_cast<__half2*>(&v.x));
            float2 b = __half22float2(*reinterpret_cast<__half2*>(&v.y));
            if (e < m) {
                acc.x += a.x; acc.y += a.y; acc.z += b.x; acc.w += b.y;
            }
        }
    }
    // combine halves: afterwards ALL lanes hold the full sums for features
    // 4*sub .. 4*sub+3
    acc.x += __shfl_xor_sync(0xffffffffu, acc.x, 16);
    acc.y += __shfl_xor_sync(0xffffffffu, acc.y, 16);
    acc.z += __shfl_xor_sync(0xffffffffu, acc.z, 16);
    acc.w += __shfl_xor_sync(0xffffffffu, acc.w, 16);

    // h row in registers (4 features per lane, duplicated across halves)
    float inv = 1.f / fmaxf((float)deg, 1.f);
    const float4* xr4 = reinterpret_cast<const float4*>(xr);
    float4 r = __ldg(&xr4[(size_t)node * 16 + sub]);
    float hv0 = fmaxf(acc.x * inv + r.x, 0.f);
    float hv1 = fmaxf(acc.y * inv + r.y, 0.f);
    float hv2 = fmaxf(acc.z * inv + r.z, 0.f);
    float hv3 = fmaxf(acc.w * inv + r.w, 0.f);

    // layer-2 GEMV: lane j<16 -> hl_j, lane j>=16 -> hr_{j-16}
    float o = (lane >= 16) ? sb2[lane - 16] : 0.f;
#pragma unroll
    for (int k = 0; k < 64; k += 4) {
        int srcl = k >> 2;  // lanes 0..15 hold the h row
        float h0 = __shfl_sync(0xffffffffu, hv0, srcl);
        float h1 = __shfl_sync(0xffffffffu, hv1, srcl);
        float h2 = __shfl_sync(0xffffffffu, hv2, srcl);
        float h3 = __shfl_sync(0xffffffffu, hv3, srcl);
        o += h0 * sW2[(k + 0) * 32 + lane] + h1 * sW2[(k + 1) * 32 + lane]
           + h2 * sW2[(k + 2) * 32 + lane] + h3 * sW2[(k + 3) * 32 + lane];
    }
    if (lane < 16) hl[(size_t)node * H2 + lane] = __float2half_rn(o);
    else           hr[(size_t)node * H2 + lane - 16] = o;
}

// ---------------- agg16_final (verbatim R14/passing) ----------------
__global__ void agg16_final_kernel(const __half* __restrict__ hl, const float* __restrict__ hr,
                                   const float* __restrict__ Wfc, const float* __restrict__ bfc,
                                   float* __restrict__ out, int n) {
    int node = blockIdx.x * 8 + (threadIdx.x >> 5);
    int lane = threadIdx.x & 31;
    int grp = lane >> 2;
    int sub = lane & 3;
    cudaGridDependencySynchronize();
    if (node >= n) return;

    int rs  = g_start[node];
    int deg = g_deg[node];
    const uint2* f = reinterpret_cast<const uint2*>(hl);

    float4 acc = make_float4(0.f, 0.f, 0.f, 0.f);
    for (int base = 0; base < deg; base += 32) {
        int m = min(32, deg - base);
        int c = (lane < m) ? __ldg(&g_col[rs + base + lane]) : 0;
#pragma unroll 4
        for (int q = 0; q < m; q += 8) {
            int e = q + grp;
            int idx = __shfl_sync(0xffffffffu, c, e);
            uint2 v = __ldg(&f[(size_t)idx * 4 + sub]);
            float2 a = __half22float2(*reinterpret_cast<__half2*>(&v.x));
            float2 b = __half22float2(*reinterpret_cast<__half2*>(&v.y));
            if (e < m) {
                acc.x += a.x; acc.y += a.y; acc.z += b.x; acc.w += b.y;
            }
        }
    }
    acc.x += __shfl_xor_sync(0xffffffffu, acc.x, 4);
    acc.y += __shfl_xor_sync(0xffffffffu, acc.y, 4);
    acc.z += __shfl_xor_sync(0xffffffffu, acc.z, 4);
    acc.w += __shfl_xor_sync(0xffffffffu, acc.w, 4);
    acc.x += __shfl_xor_sync(0xffffffffu, acc.x, 8);
    acc.y += __shfl_xor_sync(0xffffffffu, acc.y, 8);
    acc.z += __shfl_xor_sync(0xffffffffu, acc.z, 8);
    acc.w += __shfl_xor_sync(0xffffffffu, acc.w, 8);
    acc.x += __shfl_xor_sync(0xffffffffu, acc.x, 16);
    acc.y += __shfl_xor_sync(0xffffffffu, acc.y, 16);
    acc.z += __shfl_xor_sync(0xffffffffu, acc.z, 16);
    acc.w += __shfl_xor_sync(0xffffffffu, acc.w, 16);

    float inv = 1.f / fmaxf((float)deg, 1.f);
    const float4* hr4 = reinterpret_cast<const float4*>(hr);
    float4 r = __ldg(&hr4[(size_t)node * 4 + sub]);
    float a0 = acc.x * inv + r.x;
    float a1 = acc.y * inv + r.y;
    float a2 = acc.z * inv + r.z;
    float a3 = acc.w * inv + r.w;

    int jb = sub * 4;
    float o0 = a0 * __ldg(&Wfc[(jb + 0) * OUTW + 0]) + a1 * __ldg(&Wfc[(jb + 1) * OUTW + 0])
             + a2 * __ldg(&Wfc[(jb + 2) * OUTW + 0]) + a3 * __ldg(&Wfc[(jb + 3) * OUTW + 0]);
    float o1 = a0 * __ldg(&Wfc[(jb + 0) * OUTW + 1]) + a1 * __ldg(&Wfc[(jb + 1) * OUTW + 1])
             + a2 * __ldg(&Wfc[(jb + 2) * OUTW + 1]) + a3 * __ldg(&Wfc[(jb + 3) * OUTW + 1]);
    o0 += __shfl_xor_sync(0xffffffffu, o0, 1);
    o1 += __shfl_xor_sync(0xffffffffu, o1, 1);
    o0 += __shfl_xor_sync(0xffffffffu, o0, 2);
    o1 += __shfl_xor_sync(0xffffffffu, o1, 2);

    if (lane == 0) {
        out[(size_t)node * OUTW + 0] = o0 + __ldg(&bfc[0]);
        out[(size_t)node * OUTW + 1] = o1 + __ldg(&bfc[1]);
    }
}

// ---------------- launcher (single stream; PDL-chained launches) ----------------
template <typename... Args>
static void launch_pdl(void (*kernel)(Args...), int grid, Args... args) {
    cudaLaunchConfig_t cfg = {};
    cfg.gridDim  = dim3((unsigned)grid, 1, 1);
    cfg.blockDim = dim3(256, 1, 1);
    cfg.stream   = 0;
    cudaLaunchAttribute attr[1];
    attr[0].id = cudaLaunchAttributeProgrammaticStreamSerialization;
    attr[0].val.programmaticStreamSerializationAllowed = 1;
    cfg.attrs = attr;
    cfg.numAttrs = 1;
    cudaLaunchKernelEx(&cfg, kernel, args...);
}

extern "C" void kernel_launch(void* const* d_in, const int* in_sizes, int n_in,
                              void* d_out, int out_size) {
    const float* x   = (const float*)d_in[0];
    const int*   e   = (const int*)d_in[1];
    const float* W1l = (const float*)d_in[2];
    const float* b1  = (const float*)d_in[3];
    const float* W1r = (const float*)d_in[4];
    const float* W2l = (const float*)d_in[5];
    const float* b2  = (const float*)d_in[6];
    const float* W2r = (const float*)d_in[7];
    const float* Wfc = (const float*)d_in[8];
    const float* bfc = (const float*)d_in[9];
    float* out = (float*)d_out;

    int n = in_sizes[0] / D;
    int E = in_sizes[1] / 2;
    const int* src = e;
    const int* dst = e + E;

    __half *xlp, *hlp;
    float *xrp, *hrp;
    cudaGetSymbolAddress((void**)&xlp, g_xl);
    cudaGetSymbolAddress((void**)&xrp, g_xr);
    cudaGetSymbolAddress((void**)&hlp, g_hl);
    cudaGetSymbolAddress((void**)&hrp, g_hr);

    int dense0Blocks = (n + 63) / 64;
    int edgeBlocks   = (E / 8 + 255) / 256;

    dense0z_kernel<<<dense0Blocks, 256>>>(x, W1l, W1r, b1, xlp, xrp, n);

    launch_pdl(hist_kernel, edgeBlocks, dst, E);
    launch_pdl(alloc_kernel, (n + 255) / 256, n);
    launch_pdl(fill_kernel, edgeBlocks, src, dst, E);
    launch_pdl(agg64_dense12_kernel, (n + 7) / 8,
               (const __half*)xlp, (const float*)xrp, W2l, W2r, b2, hlp, hrp, n);
    launch_pdl(agg16_final_kernel, (n + 7) / 8,
               (const __half*)hlp, (const float*)hrp, Wfc, bfc, out, n);
}

// round 16
// speedup vs baseline: 1.2685x; 1.0048x over previous
#include <cuda_runtime.h>
#include <cuda_bf16.h>
#include <cuda_fp16.h>
#include <mma.h>

using namespace nvcuda;

constexpr int MAXN = 50000;
constexpr int MAXE = 1250000;
constexpr int D    = 64;
constexpr int H2   = 16;
constexpr int OUTW = 2;

// ---------------- device scratch ----------------
__device__ int    g_deg[MAXN];
__device__ int    g_start[MAXN];
__device__ int    g_rank[MAXE];
__device__ int    g_col[MAXE];
__device__ int    g_counter;
__device__ __half g_xl[(size_t)MAXN * D];
__device__ float  g_xr[(size_t)MAXN * D];
__device__ float2 g_hlf[MAXN];   // (h @ W2l) @ Wfc per node
__device__ float2 g_hrf[MAXN];   // (h @ W2r + b2) @ Wfc + bfc per node

// ---------------- hist (verbatim R15/passing) ----------------
__global__ void hist_kernel(const int* __restrict__ dst, int E) {
    int i = (blockIdx.x * blockDim.x + threadIdx.x) * 8;
    if (i + 7 < E) {
        int4 d0 = *reinterpret_cast<const int4*>(dst + i);
        int4 d1 = *reinterpret_cast<const int4*>(dst + i + 4);
        cudaGridDependencySynchronize();
        int4 r0, r1;
        r0.x = atomicAdd(&g_deg[d0.x], 1);
        r0.y = atomicAdd(&g_deg[d0.y], 1);
        r0.z = atomicAdd(&g_deg[d0.z], 1);
        r0.w = atomicAdd(&g_deg[d0.w], 1);
        r1.x = atomicAdd(&g_deg[d1.x], 1);
        r1.y = atomicAdd(&g_deg[d1.y], 1);
        r1.z = atomicAdd(&g_deg[d1.z], 1);
        r1.w = atomicAdd(&g_deg[d1.w], 1);
        *reinterpret_cast<int4*>(g_rank + i)     = r0;
        *reinterpret_cast<int4*>(g_rank + i + 4) = r1;
    } else {
        cudaGridDependencySynchronize();
        for (int k = i; k < E; k++) g_rank[k] = atomicAdd(&g_deg[dst[k]], 1);
    }
}

__global__ void alloc_kernel(int n) {
    cudaGridDependencySynchronize();
    int i = blockIdx.x * blockDim.x + threadIdx.x;
    int lane = threadIdx.x & 31;
    int deg = (i < n) ? g_deg[i] : 0;
    int incl = deg;
#pragma unroll
    for (int off = 1; off < 32; off <<= 1) {
        int v = __shfl_up_sync(0xffffffffu, incl, off);
        if (lane >= off) incl += v;
    }
    int excl = incl - deg;
    int base = 0;
    if (lane == 31) base = atomicAdd(&g_counter, incl);
    base = __shfl_sync(0xffffffffu, base, 31);
    if (i < n) g_start[i] = base + excl;
}

__global__ void fill_kernel(const int* __restrict__ src, const int* __restrict__ dst, int E) {
    int i = (blockIdx.x * blockDim.x + threadIdx.x) * 8;
    if (i + 7 < E) {
        int4 s0 = *reinterpret_cast<const int4*>(src + i);
        int4 s1 = *reinterpret_cast<const int4*>(src + i + 4);
        int4 d0 = *reinterpret_cast<const int4*>(dst + i);
        int4 d1 = *reinterpret_cast<const int4*>(dst + i + 4);
        cudaGridDependencySynchronize();
        int4 r0 = *reinterpret_cast<const int4*>(g_rank + i);
        int4 r1 = *reinterpret_cast<const int4*>(g_rank + i + 4);
        g_col[__ldg(&g_start[d0.x]) + r0.x] = s0.x;
        g_col[__ldg(&g_start[d0.y]) + r0.y] = s0.y;
        g_col[__ldg(&g_start[d0.z]) + r0.z] = s0.z;
        g_col[__ldg(&g_start[d0.w]) + r0.w] = s0.w;
        g_col[__ldg(&g_start[d1.x]) + r1.x] = s1.x;
        g_col[__ldg(&g_start[d1.y]) + r1.y] = s1.y;
        g_col[__ldg(&g_start[d1.z]) + r1.z] = s1.z;
        g_col[__ldg(&g_start[d1.w]) + r1.w] = s1.w;
    } else {
        cudaGridDependencySynchronize();
        for (int k = i; k < E; k++)
            g_col[__ldg(&g_start[dst[k]]) + g_rank[k]] = src[k];
    }
}

// ---------------- dense0z (verbatim R15/passing) ----------------
__global__ void dense0z_kernel(const float* __restrict__ x, const float* __restrict__ W1l,
                               const float* __restrict__ W1r, const float* __restrict__ b1,
                               __half* __restrict__ xl, float* __restrict__ xr, int n) {
    {
        int zi = blockIdx.x * 256 + threadIdx.x;
        if (zi < n) g_deg[zi] = 0;
        if (zi == 0) g_counter = 0;
    }

    __shared__ float sOut[64 * 128];
    __shared__ float sb[D];
    __half* sW = reinterpret_cast<__half*>(sOut);
    __half* sX = reinterpret_cast<__half*>(sOut + 4096);

    int tid = threadIdx.x;
    int base = blockIdx.x * 64;

    for (int i = tid; i < D * D; i += 256) {
        int k = i >> 6, j = i & 63;
        sW[k * 128 + j]      = __float2half_rn(W1l[i]);
        sW[k * 128 + 64 + j] = __float2half_rn(W1r[i]);
    }
    if (tid < D) sb[tid] = b1[tid];

    {
        int row  = tid >> 2;
        int col0 = (tid & 3) * 16;
        int gr = min(base + row, n - 1);
        const float4* xp = reinterpret_cast<const float4*>(x + (size_t)gr * D + col0);
#pragma unroll
        for (int q = 0; q < 4; q++) {
            float4 v = __ldg(&xp[q]);
            int c = col0 + q * 4;
            sX[row * 64 + c + 0] = __float2half_rn(v.x);
            sX[row * 64 + c + 1] = __float2half_rn(v.y);
            sX[row * 64 + c + 2] = __float2half_rn(v.z);
            sX[row * 64 + c + 3] = __float2half_rn(v.w);
        }
    }
    __syncthreads();

    int w = tid >> 5;
    int strip = w >> 1;
    int colbase = (w & 1) * 64;

    wmma::fragment<wmma::accumulator, 16, 16, 16, float> acc[4];
#pragma unroll
    for (int t = 0; t < 4; t++) wmma::fill_fragment(acc[t], 0.f);

#pragma unroll
    for (int k = 0; k < 4; k++) {
        wmma::fragment<wmma::matrix_a, 16, 16, 16, __half, wmma::row_major> a;
        wmma::load_matrix_sync(a, sX + strip * 16 * 64 + k * 16, 64);
#pragma unroll
        for (int t = 0; t < 4; t++) {
            wmma::fragment<wmma::matrix_b, 16, 16, 16, __half, wmma::row_major> b;
            wmma::load_matrix_sync(b, sW + k * 16 * 128 + colbase + t * 16, 128);
            wmma::mma_sync(acc[t], a, b, acc[t]);
        }
    }
    __syncthreads();

#pragma unroll
    for (int t = 0; t < 4; t++)
        wmma::store_matrix_sync(sOut + strip * 16 * 128 + colbase + t * 16, acc[t], 128,
                                wmma::mem_row_major);
    __syncthreads();

    for (int i = tid; i < 64 * 16; i += 256) {
        int row = i >> 4;
        int q   = i & 15;
        int gi  = base + row;
        if (gi >= n) continue;
        int j = q * 4;
        float l0 = sOut[row * 128 + j + 0];
        float l1 = sOut[row * 128 + j + 1];
        float l2 = sOut[row * 128 + j + 2];
        float l3 = sOut[row * 128 + j + 3];
        float r0 = sOut[row * 128 + 64 + j + 0] + sb[j + 0];
        float r1 = sOut[row * 128 + 64 + j + 1] + sb[j + 1];
        float r2 = sOut[row * 128 + 64 + j + 2] + sb[j + 2];
        float r3 = sOut[row * 128 + 64 + j + 3] + sb[j + 3];
        __half2 h01 = __floats2half2_rn(l0, l1);
        __half2 h23 = __floats2half2_rn(l2, l3);
        uint2 hv;
        hv.x = *reinterpret_cast<unsigned*>(&h01);
        hv.y = *reinterpret_cast<unsigned*>(&h23);
        reinterpret_cast<uint2*>(xl + (size_t)gi * D)[q] = hv;
        reinterpret_cast<float4*>(xr + (size_t)gi * D)[q] = make_float4(r0, r1, r2, r3);
    }
}

// ---------------- agg64_dense12f: gather + h-in-regs + layer2 GEMV + Wfc fold ----------------
__global__ void agg64_dense12f_kernel(const __half* __restrict__ xl, const float* __restrict__ xr,
                                      const float* __restrict__ W2l, const float* __restrict__ W2r,
                                      const float* __restrict__ b2,
                                      const float* __restrict__ Wfc, const float* __restrict__ bfc,
                                      float2* __restrict__ hlf, float2* __restrict__ hrf, int n) {
    __shared__ float sW2[64 * 32];   // [k][j]: j<16 = W2l, j>=16 = W2r
    __shared__ float sb2[H2];
    __shared__ float sWfc[H2 * OUTW];
    __shared__ float sbfc[OUTW];
    int tid = threadIdx.x;
    for (int i = tid; i < 64 * 16; i += 256) {
        int k = i >> 4, j = i & 15;
        sW2[k * 32 + j]      = W2l[k * H2 + j];
        sW2[k * 32 + 16 + j] = W2r[k * H2 + j];
    }
    if (tid < H2) sb2[tid] = b2[tid];
    if (tid < H2 * OUTW) sWfc[tid] = Wfc[tid];
    if (tid < OUTW) sbfc[tid] = bfc[tid];
    __syncthreads();
    cudaGridDependencySynchronize();   // wait: g_col (fill) + xl/xr (dense0z)

    int node = blockIdx.x * 8 + (tid >> 5);
    if (node >= n) return;
    int lane = tid & 31;
    int hf   = lane >> 4;
    int sub  = lane & 15;

    int rs  = g_start[node];
    int deg = g_deg[node];
    const uint2* f = reinterpret_cast<const uint2*>(xl);

    float4 acc = make_float4(0.f, 0.f, 0.f, 0.f);
    for (int base = 0; base < deg; base += 32) {
        int m = min(32, deg - base);
        int c = (lane < m) ? __ldg(&g_col[rs + base + lane]) : 0;
#pragma unroll 4
        for (int q = 0; q < m; q += 2) {
            int e = q + hf;
            int idx = __shfl_sync(0xffffffffu, c, e);
            uint2 v = __ldg(&f[(size_t)idx * 16 + sub]);
            float2 a = __half22float2(*reinterpret_cast<__half2*>(&v.x));
            float2 b = __half22float2(*reinterpret_cast<__half2*>(&v.y));
            if (e < m) {
                acc.x += a.x; acc.y += a.y; acc.z += b.x; acc.w += b.y;
            }
        }
    }
    acc.x += __shfl_xor_sync(0xffffffffu, acc.x, 16);
    acc.y += __shfl_xor_sync(0xffffffffu, acc.y, 16);
    acc.z += __shfl_xor_sync(0xffffffffu, acc.z, 16);
    acc.w += __shfl_xor_sync(0xffffffffu, acc.w, 16);

    float inv = 1.f / fmaxf((float)deg, 1.f);
    const float4* xr4 = reinterpret_cast<const float4*>(xr);
    float4 r = __ldg(&xr4[(size_t)node * 16 + sub]);
    float hv0 = fmaxf(acc.x * inv + r.x, 0.f);
    float hv1 = fmaxf(acc.y * inv + r.y, 0.f);
    float hv2 = fmaxf(acc.z * inv + r.z, 0.f);
    float hv3 = fmaxf(acc.w * inv + r.w, 0.f);

    // layer-2 GEMV: lane j<16 -> hl_j, lane j>=16 -> hr_{j-16} (with b2)
    float o = (lane >= 16) ? sb2[lane - 16] : 0.f;
#pragma unroll
    for (int k = 0; k < 64; k += 4) {
        int srcl = k >> 2;
        float h0 = __shfl_sync(0xffffffffu, hv0, srcl);
        float h1 = __shfl_sync(0xffffffffu, hv1, srcl);
        float h2 = __shfl_sync(0xffffffffu, hv2, srcl);
        float h3 = __shfl_sync(0xffffffffu, hv3, srcl);
        o += h0 * sW2[(k + 0) * 32 + lane] + h1 * sW2[(k + 1) * 32 + lane]
           + h2 * sW2[(k + 2) * 32 + lane] + h3 * sW2[(k + 3) * 32 + lane];
    }

    // fold Wfc: c = o * Wfc[j][:], reduce within each 16-lane half
    int j = lane & 15;
    float c0 = o * sWfc[j * OUTW + 0];
    float c1 = o * sWfc[j * OUTW + 1];
#pragma unroll
    for (int off = 8; off >= 1; off >>= 1) {
        c0 += __shfl_xor_sync(0xffffffffu, c0, off);
        c1 += __shfl_xor_sync(0xffffffffu, c1, off);
    }
    if (lane == 0)  hlf[node] = make_float2(c0, c1);
    if (lane == 16) hrf[node] = make_float2(c0 + sbfc[0], c1 + sbfc[1]);
}

// ---------------- agg2f_final: out = mean-gather(hlf) + hrf ----------------
// Warp per node; one edge per lane (8B float2), no per-edge shfl.
__global__ void agg2f_final_kernel(const float2* __restrict__ hlf, const float2* __restrict__ hrf,
                                   float* __restrict__ out, int n) {
    int node = blockIdx.x * 8 + (threadIdx.x >> 5);
    int lane = threadIdx.x & 31;
    cudaGridDependencySynchronize();
    if (node >= n) return;

    int rs  = g_start[node];
    int deg = g_deg[node];

    float a0 = 0.f, a1 = 0.f;
    for (int base = 0; base < deg; base += 32) {
        int m = min(32, deg - base);
        if (lane < m) {
            int c = __ldg(&g_col[rs + base + lane]);
            float2 v = __ldg(&hlf[c]);
            a0 += v.x; a1 += v.y;
        }
    }
#pragma unroll
    for (int off = 16; off >= 1; off >>= 1) {
        a0 += __shfl_xor_sync(0xffffffffu, a0, off);
        a1 += __shfl_xor_sync(0xffffffffu, a1, off);
    }
    if (lane == 0) {
        float inv = 1.f / fmaxf((float)deg, 1.f);
        float2 r = __ldg(&hrf[node]);
        reinterpret_cast<float2*>(out)[node] = make_float2(a0 * inv + r.x, a1 * inv + r.y);
    }
}

// ---------------- launcher (single stream; PDL-chained launches) ----------------
template <typename... Args>
static void launch_pdl(void (*kernel)(Args...), int grid, Args... args) {
    cudaLaunchConfig_t cfg = {};
    cfg.gridDim  = dim3((unsigned)grid, 1, 1);
    cfg.blockDim = dim3(256, 1, 1);
    cfg.stream   = 0;
    cudaLaunchAttribute attr[1];
    attr[0].id = cudaLaunchAttributeProgrammaticStreamSerialization;
    attr[0].val.programmaticStreamSerializationAllowed = 1;
    cfg.attrs = attr;
    cfg.numAttrs = 1;
    cudaLaunchKernelEx(&cfg, kernel, args...);
}

extern "C" void kernel_launch(void* const* d_in, const int* in_sizes, int n_in,
                              void* d_out, int out_size) {
    const float* x   = (const float*)d_in[0];
    const int*   e   = (const int*)d_in[1];
    const float* W1l = (const float*)d_in[2];
    const float* b1  = (const float*)d_in[3];
    const float* W1r = (const float*)d_in[4];
    const float* W2l = (const float*)d_in[5];
    const float* b2  = (const float*)d_in[6];
    const float* W2r = (const float*)d_in[7];
    const float* Wfc = (const float*)d_in[8];
    const float* bfc = (const float*)d_in[9];
    float* out = (float*)d_out;

    int n = in_sizes[0] / D;
    int E = in_sizes[1] / 2;
    const int* src = e;
    const int* dst = e + E;

    __half* xlp;
    float* xrp;
    float2 *hlfp, *hrfp;
    cudaGetSymbolAddress((void**)&xlp, g_xl);
    cudaGetSymbolAddress((void**)&xrp, g_xr);
    cudaGetSymbolAddress((void**)&hlfp, g_hlf);
    cudaGetSymbolAddress((void**)&hrfp, g_hrf);

    int dense0Blocks = (n + 63) / 64;
    int edgeBlocks   = (E / 8 + 255) / 256;

    dense0z_kernel<<<dense0Blocks, 256>>>(x, W1l, W1r, b1, xlp, xrp, n);

    launch_pdl(hist_kernel, edgeBlocks, dst, E);
    launch_pdl(alloc_kernel, (n + 255) / 256, n);
    launch_pdl(fill_kernel, edgeBlocks, src, dst, E);
    launch_pdl(agg64_dense12f_kernel, (n + 7) / 8,
               (const __half*)xlp, (const float*)xrp, W2l, W2r, b2, Wfc, bfc,
               hlfp, hrfp, n);
    launch_pdl(agg2f_final_kernel, (n + 7) / 8,
               (const float2*)hlfp, (const float2*)hrfp, out, n);
}

// round 17
// speedup vs baseline: 1.2709x; 1.0019x over previous
#include <cuda_runtime.h>
#include <cuda_bf16.h>
#include <cuda_fp16.h>
#include <mma.h>

using namespace nvcuda;

constexpr int MAXN = 50000;
constexpr int MAXE = 1250000;
constexpr int D    = 64;
constexpr int H2   = 16;
constexpr int OUTW = 2;

// ---------------- device scratch ----------------
__device__ int    g_deg[MAXN];
__device__ int    g_start[MAXN];
__device__ int    g_rank[MAXE];
__device__ int    g_col[MAXE];
__device__ int    g_counter;
__device__ __half g_xl[(size_t)MAXN * D];
__device__ float  g_xr[(size_t)MAXN * D];
__device__ float2 g_hlf[MAXN];
__device__ float2 g_hrf[MAXN];

// ---------------- hist (4 edges/thread) ----------------
__global__ void hist_kernel(const int* __restrict__ dst, int E) {
    int i = (blockIdx.x * blockDim.x + threadIdx.x) * 4;
    if (i + 3 < E) {
        int4 d0 = *reinterpret_cast<const int4*>(dst + i);
        cudaGridDependencySynchronize();   // wait: g_deg zeroed (dense0z trigger)
        int4 r0;
        r0.x = atomicAdd(&g_deg[d0.x], 1);
        r0.y = atomicAdd(&g_deg[d0.y], 1);
        r0.z = atomicAdd(&g_deg[d0.z], 1);
        r0.w = atomicAdd(&g_deg[d0.w], 1);
        *reinterpret_cast<int4*>(g_rank + i) = r0;
    } else {
        cudaGridDependencySynchronize();
        for (int k = i; k < E; k++) g_rank[k] = atomicAdd(&g_deg[dst[k]], 1);
    }
}

__global__ void alloc_kernel(int n) {
    cudaGridDependencySynchronize();
    int i = blockIdx.x * blockDim.x + threadIdx.x;
    int lane = threadIdx.x & 31;
    int deg = (i < n) ? g_deg[i] : 0;
    int incl = deg;
#pragma unroll
    for (int off = 1; off < 32; off <<= 1) {
        int v = __shfl_up_sync(0xffffffffu, incl, off);
        if (lane >= off) incl += v;
    }
    int excl = incl - deg;
    int base = 0;
    if (lane == 31) base = atomicAdd(&g_counter, incl);
    base = __shfl_sync(0xffffffffu, base, 31);
    if (i < n) g_start[i] = base + excl;
}

// ---------------- fill (4 edges/thread, atomic-free) ----------------
__global__ void fill_kernel(const int* __restrict__ src, const int* __restrict__ dst, int E) {
    int i = (blockIdx.x * blockDim.x + threadIdx.x) * 4;
    if (i + 3 < E) {
        int4 s0 = *reinterpret_cast<const int4*>(src + i);
        int4 d0 = *reinterpret_cast<const int4*>(dst + i);
        cudaGridDependencySynchronize();   // wait: g_start (alloc)
        int4 r0 = *reinterpret_cast<const int4*>(g_rank + i);
        g_col[__ldg(&g_start[d0.x]) + r0.x] = s0.x;
        g_col[__ldg(&g_start[d0.y]) + r0.y] = s0.y;
        g_col[__ldg(&g_start[d0.z]) + r0.z] = s0.z;
        g_col[__ldg(&g_start[d0.w]) + r0.w] = s0.w;
    } else {
        cudaGridDependencySynchronize();
        for (int k = i; k < E; k++)
            g_col[__ldg(&g_start[dst[k]]) + g_rank[k]] = src[k];
    }
}

// ---------------- dense0z: zero + EARLY TRIGGER + wmma GEMM ----------------
__global__ void dense0z_kernel(const float* __restrict__ x, const float* __restrict__ W1l,
                               const float* __restrict__ W1r, const float* __restrict__ b1,
                               __half* __restrict__ xl, float* __restrict__ xr, int n) {
    // zero prologue (grid*256 >= n), then release dependent (hist) early
    {
        int zi = blockIdx.x * 256 + threadIdx.x;
        if (zi < n) g_deg[zi] = 0;
        if (zi == 0) g_counter = 0;
        __threadfence();
        cudaTriggerProgrammaticLaunchCompletion();
    }

    __shared__ float sOut[64 * 128];
    __shared__ float sb[D];
    __half* sW = reinterpret_cast<__half*>(sOut);
    __half* sX = reinterpret_cast<__half*>(sOut + 4096);

    int tid = threadIdx.x;
    int base = blockIdx.x * 64;

    for (int i = tid; i < D * D; i += 256) {
        int k = i >> 6, j = i & 63;
        sW[k * 128 + j]      = __float2half_rn(W1l[i]);
        sW[k * 128 + 64 + j] = __float2half_rn(W1r[i]);
    }
    if (tid < D) sb[tid] = b1[tid];

    {
        int row  = tid >> 2;
        int col0 = (tid & 3) * 16;
        int gr = min(base + row, n - 1);
        const float4* xp = reinterpret_cast<const float4*>(x + (size_t)gr * D + col0);
#pragma unroll
        for (int q = 0; q < 4; q++) {
            float4 v = __ldg(&xp[q]);
            int c = col0 + q * 4;
            sX[row * 64 + c + 0] = __float2half_rn(v.x);
            sX[row * 64 + c + 1] = __float2half_rn(v.y);
            sX[row * 64 + c + 2] = __float2half_rn(v.z);
            sX[row * 64 + c + 3] = __float2half_rn(v.w);
        }
    }
    __syncthreads();

    int w = tid >> 5;
    int strip = w >> 1;
    int colbase = (w & 1) * 64;

    wmma::fragment<wmma::accumulator, 16, 16, 16, float> acc[4];
#pragma unroll
    for (int t = 0; t < 4; t++) wmma::fill_fragment(acc[t], 0.f);

#pragma unroll
    for (int k = 0; k < 4; k++) {
        wmma::fragment<wmma::matrix_a, 16, 16, 16, __half, wmma::row_major> a;
        wmma::load_matrix_sync(a, sX + strip * 16 * 64 + k * 16, 64);
#pragma unroll
        for (int t = 0; t < 4; t++) {
            wmma::fragment<wmma::matrix_b, 16, 16, 16, __half, wmma::row_major> b;
            wmma::load_matrix_sync(b, sW + k * 16 * 128 + colbase + t * 16, 128);
            wmma::mma_sync(acc[t], a, b, acc[t]);
        }
    }
    __syncthreads();

#pragma unroll
    for (int t = 0; t < 4; t++)
        wmma::store_matrix_sync(sOut + strip * 16 * 128 + colbase + t * 16, acc[t], 128,
                                wmma::mem_row_major);
    __syncthreads();

    for (int i = tid; i < 64 * 16; i += 256) {
        int row = i >> 4;
        int q   = i & 15;
        int gi  = base + row;
        if (gi >= n) continue;
        int j = q * 4;
        float l0 = sOut[row * 128 + j + 0];
        float l1 = sOut[row * 128 + j + 1];
        float l2 = sOut[row * 128 + j + 2];
        float l3 = sOut[row * 128 + j + 3];
        float r0 = sOut[row * 128 + 64 + j + 0] + sb[j + 0];
        float r1 = sOut[row * 128 + 64 + j + 1] + sb[j + 1];
        float r2 = sOut[row * 128 + 64 + j + 2] + sb[j + 2];
        float r3 = sOut[row * 128 + 64 + j + 3] + sb[j + 3];
        __half2 h01 = __floats2half2_rn(l0, l1);
        __half2 h23 = __floats2half2_rn(l2, l3);
        uint2 hv;
        hv.x = *reinterpret_cast<unsigned*>(&h01);
        hv.y = *reinterpret_cast<unsigned*>(&h23);
        reinterpret_cast<uint2*>(xl + (size_t)gi * D)[q] = hv;
        reinterpret_cast<float4*>(xr + (size_t)gi * D)[q] = make_float4(r0, r1, r2, r3);
    }
}

// ---------------- agg64_dense12f (verbatim R16; launched REGULAR = full barrier) ----------------
__global__ void agg64_dense12f_kernel(const __half* __restrict__ xl, const float* __restrict__ xr,
                                      const float* __restrict__ W2l, const float* __restrict__ W2r,
                                      const float* __restrict__ b2,
                                      const float* __restrict__ Wfc, const float* __restrict__ bfc,
                                      float2* __restrict__ hlf, float2* __restrict__ hrf, int n) {
    __shared__ float sW2[64 * 32];
    __shared__ float sb2[H2];
    __shared__ float sWfc[H2 * OUTW];
    __shared__ float sbfc[OUTW];
    int tid = threadIdx.x;
    for (int i = tid; i < 64 * 16; i += 256) {
        int k = i >> 4, j = i & 15;
        sW2[k * 32 + j]      = W2l[k * H2 + j];
        sW2[k * 32 + 16 + j] = W2r[k * H2 + j];
    }
    if (tid < H2) sb2[tid] = b2[tid];
    if (tid < H2 * OUTW) sWfc[tid] = Wfc[tid];
    if (tid < OUTW) sbfc[tid] = bfc[tid];
    __syncthreads();

    int node = blockIdx.x * 8 + (tid >> 5);
    if (node >= n) return;
    int lane = tid & 31;
    int hf   = lane >> 4;
    int sub  = lane & 15;

    int rs  = g_start[node];
    int deg = g_deg[node];
    const uint2* f = reinterpret_cast<const uint2*>(xl);

    float4 acc = make_float4(0.f, 0.f, 0.f, 0.f);
    for (int base = 0; base < deg; base += 32) {
        int m = min(32, deg - base);
        int c = (lane < m) ? __ldg(&g_col[rs + base + lane]) : 0;
#pragma unroll 4
        for (int q = 0; q < m; q += 2) {
            int e = q + hf;
            int idx = __shfl_sync(0xffffffffu, c, e);
            uint2 v = __ldg(&f[(size_t)idx * 16 + sub]);
            float2 a = __half22float2(*reinterpret_cast<__half2*>(&v.x));
            float2 b = __half22float2(*reinterpret_cast<__half2*>(&v.y));
            if (e < m) {
                acc.x += a.x; acc.y += a.y; acc.z += b.x; acc.w += b.y;
            }
        }
    }
    acc.x += __shfl_xor_sync(0xffffffffu, acc.x, 16);
    acc.y += __shfl_xor_sync(0xffffffffu, acc.y, 16);
    acc.z += __shfl_xor_sync(0xffffffffu, acc.z, 16);
    acc.w += __shfl_xor_sync(0xffffffffu, acc.w, 16);

    float inv = 1.f / fmaxf((float)deg, 1.f);
    const float4* xr4 = reinterpret_cast<const float4*>(xr);
    float4 r = __ldg(&xr4[(size_t)node * 16 + sub]);
    float hv0 = fmaxf(acc.x * inv + r.x, 0.f);
    float hv1 = fmaxf(acc.y * inv + r.y, 0.f);
    float hv2 = fmaxf(acc.z * inv + r.z, 0.f);
    float hv3 = fmaxf(acc.w * inv + r.w, 0.f);

    float o = (lane >= 16) ? sb2[lane - 16] : 0.f;
#pragma unroll
    for (int k = 0; k < 64; k += 4) {
        int srcl = k >> 2;
        float h0 = __shfl_sync(0xffffffffu, hv0, srcl);
        float h1 = __shfl_sync(0xffffffffu, hv1, srcl);
        float h2 = __shfl_sync(0xffffffffu, hv2, srcl);
        float h3 = __shfl_sync(0xffffffffu, hv3, srcl);
        o += h0 * sW2[(k + 0) * 32 + lane] + h1 * sW2[(k + 1) * 32 + lane]
           + h2 * sW2[(k + 2) * 32 + lane] + h3 * sW2[(k + 3) * 32 + lane];
    }

    int j = lane & 15;
    float c0 = o * sWfc[j * OUTW + 0];
    float c1 = o * sWfc[j * OUTW + 1];
#pragma unroll
    for (int off = 8; off >= 1; off >>= 1) {
        c0 += __shfl_xor_sync(0xffffffffu, c0, off);
        c1 += __shfl_xor_sync(0xffffffffu, c1, off);
    }
    if (lane == 0)  hlf[node] = make_float2(c0, c1);
    if (lane == 16) hrf[node] = make_float2(c0 + sbfc[0], c1 + sbfc[1]);
}

// ---------------- agg2f_final (verbatim R16) ----------------
__global__ void agg2f_final_kernel(const float2* __restrict__ hlf, const float2* __restrict__ hrf,
                                   float* __restrict__ out, int n) {
    int node = blockIdx.x * 8 + (threadIdx.x >> 5);
    int lane = threadIdx.x & 31;
    cudaGridDependencySynchronize();
    if (node >= n) return;

    int rs  = g_start[node];
    int deg = g_deg[node];

    float a0 = 0.f, a1 = 0.f;
    for (int base = 0; base < deg; base += 32) {
        int m = min(32, deg - base);
        if (lane < m) {
            int c = __ldg(&g_col[rs + base + lane]);
            float2 v = __ldg(&hlf[c]);
            a0 += v.x; a1 += v.y;
        }
    }
#pragma unroll
    for (int off = 16; off >= 1; off >>= 1) {
        a0 += __shfl_xor_sync(0xffffffffu, a0, off);
        a1 += __shfl_xor_sync(0xffffffffu, a1, off);
    }
    if (lane == 0) {
        float inv = 1.f / fmaxf((float)deg, 1.f);
        float2 r = __ldg(&hrf[node]);
        reinterpret_cast<float2*>(out)[node] = make_float2(a0 * inv + r.x, a1 * inv + r.y);
    }
}

// ---------------- launcher ----------------
template <typename... Args>
static void launch_pdl(void (*kernel)(Args...), int grid, Args... args) {
    cudaLaunchConfig_t cfg = {};
    cfg.gridDim  = dim3((unsigned)grid, 1, 1);
    cfg.blockDim = dim3(256, 1, 1);
    cfg.stream   = 0;
    cudaLaunchAttribute attr[1];
    attr[0].id = cudaLaunchAttributeProgrammaticStreamSerialization;
    attr[0].val.programmaticStreamSerializationAllowed = 1;
    cfg.attrs = attr;
    cfg.numAttrs = 1;
    cudaLaunchKernelEx(&cfg, kernel, args...);
}

extern "C" void kernel_launch(void* const* d_in, const int* in_sizes, int n_in,
                              void* d_out, int out_size) {
    const float* x   = (const float*)d_in[0];
    const int*   e   = (const int*)d_in[1];
    const float* W1l = (const float*)d_in[2];
    const float* b1  = (const float*)d_in[3];
    const float* W1r = (const float*)d_in[4];
    const float* W2l = (const float*)d_in[5];
    const float* b2  = (const float*)d_in[6];
    const float* W2r = (const float*)d_in[7];
    const float* Wfc = (const float*)d_in[8];
    const float* bfc = (const float*)d_in[9];
    float* out = (float*)d_out;

    int n = in_sizes[0] / D;
    int E = in_sizes[1] / 2;
    const int* src = e;
    const int* dst = e + E;

    __half* xlp;
    float* xrp;
    float2 *hlfp, *hrfp;
    cudaGetSymbolAddress((void**)&xlp, g_xl);
    cudaGetSymbolAddress((void**)&xrp, g_xr);
    cudaGetSymbolAddress((void**)&hlfp, g_hlf);
    cudaGetSymbolAddress((void**)&hrfp, g_hrf);

    int dense0Blocks = (n + 63) / 64;
    int edgeBlocks4  = (E / 4 + 255) / 256;

    // dense0z zeroes g_deg, triggers early, then computes GEMM — hist overlaps it.
    dense0z_kernel<<<dense0Blocks, 256>>>(x, W1l, W1r, b1, xlp, xrp, n);

    launch_pdl(hist_kernel, edgeBlocks4, dst, E);
    launch_pdl(alloc_kernel, (n + 255) / 256, n);
    launch_pdl(fill_kernel, edgeBlocks4, src, dst, E);

    // REGULAR launch: full stream barrier — guarantees dense0z (xl/xr) AND fill
    // (g_col) are complete despite dense0z's early trigger upstream.
    agg64_dense12f_kernel<<<(n + 7) / 8, 256>>>(
        (const __half*)xlp, (const float*)xrp, W2l, W2r, b2, Wfc, bfc,
        hlfp, hrfp, n);

    launch_pdl(agg2f_final_kernel, (n + 7) / 8,
               (const float2*)hlfp, (const float2*)hrfp, out, n);
}